// round 11
// baseline (speedup 1.0000x reference)
#include <cuda_runtime.h>
#include <cuda_bf16.h>
#include <cstdint>

#define Bsz 2
#define Ssz 4096
#define Hsz 16
#define DK  128
#define CC  64
#define NCH (Ssz/CC)      // 64 chunks
#define BH  (Bsz*Hsz)     // 32
#define CCP 68            // phase1 transposed row pad
#define SPLIT 4
#define DVS (DK/SPLIT)    // 32
#define ATP 68            // phase2 attnT row pad
#define VNP 36            // phase2 DVS-wide row pad
#define REDW 20           // reduction row stride

// -------- scratch (device globals: allocation-free rule) --------
__device__ float g_qg[(size_t)BH*Ssz*DK];   // normalized q * Dk^-0.5 * exp(gcs)
__device__ float g_kn[(size_t)BH*Ssz*DK];   // normalized k
__device__ float g_u [(size_t)BH*Ssz*DK];   // Tinv @ (v*beta)
__device__ float g_w [(size_t)BH*Ssz*DK];   // Tinv @ (k*beta*exp(gcs))  (kcd)
__device__ float g_at[(size_t)BH*Ssz*CC];   // intra-chunk attn TRANSPOSED: [j][i]
__device__ float g_gc[(size_t)BH*Ssz];      // within-chunk cumsum of g

// 16B async copy global->shared
__device__ __forceinline__ void cpa16(void* dst, const void* src) {
  unsigned d = (unsigned)__cvta_generic_to_shared(dst);
  asm volatile("cp.async.cg.shared.global [%0], [%1], 16;" :: "r"(d), "l"(src));
}
__device__ __forceinline__ void cpa_commit() {
  asm volatile("cp.async.commit_group;");
}
template<int N> __device__ __forceinline__ void cpa_wait() {
  asm volatile("cp.async.wait_group %0;" :: "n"(N) : "memory");
}

// XOR bank swizzle for kc/qg tiles (row stride 128 floats; c4 in float4 units)
__device__ __forceinline__ int swz(int r, int c4) {
  return (r << 7) + ((c4 ^ ((r >> 2) & 3)) << 2);
}

struct P1S {
  float knT[DK][CCP];
  float qgT[DK][CCP];
  float A  [CC][CC];
  float gcs[CC];
  float bet[CC];
  float eg[CC];
  float er[CC];
  float ebg[CC];
};

struct P2S {
  float st [DK][VNP];      // state slice [DK][DVS]
  float kn [CC*DK];        // stride 128, unswizzled
  float kc [CC*DK];        // swizzled
  float qg [CC*DK];        // swizzled
  float uu [CC][VNP];
  float atT[CC][ATP];      // attn transposed [j][i]
  float vn [CC][VNP];
  float vnw[CC][VNP];      // vn * exp(g_last - gcs_i)
  float red[3][128][REDW]; // split-K partials (quarters 1..3)
  float w  [CC];
  float elv;               // exp(g_last)
};

// ================= Phase 1: per-chunk precompute (grid = BH*NCH) =================
__global__ void __launch_bounds__(256, 2) phase1_kernel(
    const float* __restrict__ q, const float* __restrict__ k,
    const float* __restrict__ v, const float* __restrict__ g,
    const float* __restrict__ beta)
{
  extern __shared__ char smraw[];
  P1S& s = *reinterpret_cast<P1S*>(smraw);
  const int t    = threadIdx.x;
  const int lane = t & 31;
  const int warp = t >> 5;
  const int cid = blockIdx.x;
  const int bh = cid / NCH, n = cid % NCH;
  const int b = bh / Hsz, h = bh % Hsz;
  const int s0 = n * CC;

  if (t < CC) {
    s.bet[t] = beta[(size_t)(b*Ssz + s0 + t)*Hsz + h];
    s.gcs[t] = g   [(size_t)(b*Ssz + s0 + t)*Hsz + h];
  }
  __syncthreads();
  if (t < CC) {
    float x = s.gcs[t];
    #pragma unroll
    for (int o = 1; o < 32; o <<= 1) {
      float y = __shfl_up_sync(0xffffffffu, x, o);
      if (lane >= o) x += y;
    }
    s.gcs[t] = x;
  }
  __syncthreads();
  if (t < CC) {
    float gi = s.gcs[t];
    if (t >= 32) { gi += s.gcs[31]; s.gcs[t] = gi; }
    const float e = __expf(gi);
    s.eg[t]  = e;
    s.er[t]  = __expf(-gi);
    s.ebg[t] = s.bet[t] * e;
    g_gc[(size_t)bh*Ssz + s0 + t] = gi;
  }
  __syncthreads();

  for (int r = warp; r < CC; r += 8) {
    const size_t base = ((size_t)(b*Ssz + s0 + r)*Hsz + h)*DK;
    float kv[4], qv[4];
    float ssk = 0.f, ssq = 0.f;
    #pragma unroll
    for (int i = 0; i < 4; i++) {
      kv[i] = k[base + lane + 32*i]; ssk = fmaf(kv[i], kv[i], ssk);
      qv[i] = q[base + lane + 32*i]; ssq = fmaf(qv[i], qv[i], ssq);
    }
    #pragma unroll
    for (int o = 16; o; o >>= 1) {
      ssk += __shfl_xor_sync(0xffffffffu, ssk, o);
      ssq += __shfl_xor_sync(0xffffffffu, ssq, o);
    }
    const float rk = rsqrtf(ssk + 1e-6f);
    const float rq = rsqrtf(ssq + 1e-6f) * 0.08838834764831845f * s.eg[r];
    const size_t ob = ((size_t)bh*Ssz + s0 + r)*DK;
    #pragma unroll
    for (int i = 0; i < 4; i++) {
      const int d = lane + 32*i;
      const float kk = kv[i]*rk, qq = qv[i]*rq;
      s.knT[d][r] = kk; g_kn[ob + d] = kk;
      s.qgT[d][r] = qq; g_qg[ob + d] = qq;
    }
  }
  __syncthreads();

  // ---- GEMM: A (strict lower) + attn (tril) stored TRANSPOSED ----
  {
    const int ti = t >> 4, tj = t & 15;
    const size_t atb = ((size_t)bh*Ssz + s0)*CC;
    if (tj <= ti) {
      float accA[4][4] = {}, accT[4][4] = {};
      #pragma unroll 4
      for (int d = 0; d < DK; d++) {
        const float4 kd4 = *reinterpret_cast<const float4*>(&s.knT[d][ti*4]);
        const float4 qd4 = *reinterpret_cast<const float4*>(&s.qgT[d][ti*4]);
        const float4 kj4 = *reinterpret_cast<const float4*>(&s.knT[d][tj*4]);
        const float kd[4] = {kd4.x, kd4.y, kd4.z, kd4.w};
        const float qd[4] = {qd4.x, qd4.y, qd4.z, qd4.w};
        const float kj[4] = {kj4.x, kj4.y, kj4.z, kj4.w};
        #pragma unroll
        for (int a = 0; a < 4; a++)
          #pragma unroll
          for (int c = 0; c < 4; c++) {
            accA[a][c] = fmaf(kd[a], kj[c], accA[a][c]);
            accT[a][c] = fmaf(qd[a], kj[c], accT[a][c]);
          }
      }
      const float erj[4] = {s.er[tj*4], s.er[tj*4+1], s.er[tj*4+2], s.er[tj*4+3]};
      #pragma unroll
      for (int a = 0; a < 4; a++) {
        const int i = ti*4 + a;
        const float bei = s.bet[i] * s.eg[i];
        float4 av; float* ap = &av.x;
        #pragma unroll
        for (int c = 0; c < 4; c++) {
          const int j = tj*4 + c;
          ap[c] = (j < i) ? accA[a][c]*bei*erj[c] : 0.f;
        }
        *reinterpret_cast<float4*>(&s.A[i][tj*4]) = av;
      }
      #pragma unroll
      for (int c = 0; c < 4; c++) {
        const int j = tj*4 + c;
        float4 tv; float* tp = &tv.x;
        #pragma unroll
        for (int a = 0; a < 4; a++) {
          const int i = ti*4 + a;
          tp[a] = (j <= i) ? accT[a][c]*erj[c] : 0.f;
        }
        *reinterpret_cast<float4*>(&g_at[atb + (size_t)j*CC + ti*4]) = tv;
      }
    } else {
      const float4 z = {0.f, 0.f, 0.f, 0.f};
      #pragma unroll
      for (int a = 0; a < 4; a++)
        *reinterpret_cast<float4*>(&s.A[ti*4 + a][tj*4]) = z;
      #pragma unroll
      for (int c = 0; c < 4; c++)
        *reinterpret_cast<float4*>(&g_at[atb + (size_t)(tj*4 + c)*CC + ti*4]) = z;
    }
  }
  __syncthreads();

  float xr[CC];
  if (t < DK) {
    #pragma unroll 8
    for (int i = 0; i < CC; i++)
      xr[i] = v[((size_t)(b*Ssz + s0 + i)*Hsz + h)*DK + t] * s.bet[i];
  } else {
    const int d = t - DK;
    #pragma unroll 8
    for (int i = 0; i < CC; i++)
      xr[i] = s.knT[d][i] * s.ebg[i];
  }

  #pragma unroll
  for (int i = 1; i < CC; i++) {
    const float4* Ai = reinterpret_cast<const float4*>(&s.A[i][0]);
    float a0 = 0.f, a1 = 0.f, a2 = 0.f, a3 = 0.f;
    const int nq = (i + 3) >> 2;
    #pragma unroll
    for (int j4 = 0; j4 < nq; j4++) {
      const float4 av = Ai[j4];
      a0 = fmaf(av.x, xr[j4*4+0], a0);
      a1 = fmaf(av.y, xr[j4*4+1], a1);
      a2 = fmaf(av.z, xr[j4*4+2], a2);
      a3 = fmaf(av.w, xr[j4*4+3], a3);
    }
    xr[i] -= (a0 + a1) + (a2 + a3);
  }

  {
    const size_t ob = ((size_t)bh*Ssz + s0)*DK;
    if (t < DK) {
      #pragma unroll 8
      for (int i = 0; i < CC; i++) g_u[ob + (size_t)i*DK + t] = xr[i];
    } else {
      const int d = t - DK;
      #pragma unroll 8
      for (int i = 0; i < CC; i++) g_w[ob + (size_t)i*DK + d] = xr[i];
    }
  }
}

// ===== Phase 2: scan (BH*SPLIT CTAs, 512 thr, 3-group rotating cp.async) =====
__global__ void __launch_bounds__(512, 1) phase2_kernel(float* __restrict__ out)
{
  extern __shared__ char smraw[];
  P2S& s = *reinterpret_cast<P2S*>(smraw);
  const int t  = threadIdx.x;
  const int bh = blockIdx.x / SPLIT;
  const int sp = blockIdx.x % SPLIT;
  const int b = bh / Hsz, h = bh % Hsz;
  const int v0 = sp * DVS;

  for (int i = t; i < DK*VNP; i += 512) (&s.st[0][0])[i] = 0.f;

  const int kh = t >> 7;        // d-quarter / split phase (0..3)
  const int th = t & 127;
  const int rg = th >> 3;       // 16 row groups (stages B/C)
  const int rgl = rg & 3;       // per-thread swizzle key
  const int r0 = rg * 4;
  const int vv = (th & 7) * 4;  // 4 cols
  const int d0D = (t >> 3) * 2; // stage D: 64 d-groups x 2 rows
  const int vvD = (t & 7) * 4;

  const size_t cb = (size_t)bh*Ssz;

  // ---- prologue: A(0) = {kc,qg,uu},  B(0) = {atT} ----
  {
    const float* gw = g_w  + cb*DK;
    const float* gq = g_qg + cb*DK;
    #pragma unroll
    for (int rep = 0; rep < 4; rep++) {
      const int idx = t + rep*512;
      const int so = swz(idx >> 5, idx & 31);
      cpa16(&s.kc[so], gw + idx*4);
      cpa16(&s.qg[so], gq + idx*4);
    }
    { const int rr = t >> 3, c4 = (t & 7)*4;
      cpa16(&s.uu[rr][c4], g_u + (cb + rr)*DK + v0 + c4); }
    cpa_commit();                                   // A(0)
    #pragma unroll
    for (int rep = 0; rep < 2; rep++) {
      const int idx = t + rep*512;
      cpa16(&s.atT[idx >> 4][(idx & 15)*4], g_at + cb*CC + idx*4);
    }
    cpa_commit();                                   // B(0)
  }

  for (int n = 0; n < NCH; n++) {
    const size_t rb = cb + n*CC;
    __syncthreads();  // (1) prev-chunk stage D done: kn buffer free

    // ---- C(n): kn(n) ----
    {
      const float* gk = g_kn + rb*DK;
      #pragma unroll
      for (int rep = 0; rep < 4; rep++) {
        const int idx = t + rep*512;
        cpa16(&s.kn[idx*4], gk + idx*4);
      }
      cpa_commit();
    }
    cpa_wait<2>();    // A(n) landed: kc/qg/uu
    __syncthreads();  // (2) publish
    if (t < CC) {
      const float gl = g_gc[rb + CC - 1];
      s.w[t] = __expf(gl - g_gc[rb + t]);
      if (t == CC-1) s.elv = __expf(gl);
    }

    // ---- stage B: va = -kc@st ; oa = qg@st  (quarter kh: 32 d's) ----
    float va[4][4] = {}, oa[4][4] = {};
    #pragma unroll 2
    for (int d4 = 0; d4 < 8; d4++) {
      const int c4b = kh*8 + d4;
      const int d = c4b*4;
      const int co = (c4b ^ rgl) << 2;   // swizzled column offset (floats)
      float stc[4][4];
      #pragma unroll
      for (int m = 0; m < 4; m++) {
        const float4 s4 = *reinterpret_cast<const float4*>(&s.st[d+m][vv]);
        stc[m][0]=s4.x; stc[m][1]=s4.y; stc[m][2]=s4.z; stc[m][3]=s4.w;
      }
      #pragma unroll
      for (int a = 0; a < 4; a++) {
        const int ofs = ((r0+a) << 7) + co;
        const float4 kc4 = *reinterpret_cast<const float4*>(&s.kc[ofs]);
        const float4 qg4 = *reinterpret_cast<const float4*>(&s.qg[ofs]);
        const float kcm[4] = {kc4.x, kc4.y, kc4.z, kc4.w};
        const float qgm[4] = {qg4.x, qg4.y, qg4.z, qg4.w};
        #pragma unroll
        for (int m = 0; m < 4; m++)
          #pragma unroll
          for (int c = 0; c < 4; c++) {
            va[a][c] = fmaf(-kcm[m], stc[m][c], va[a][c]);
            oa[a][c] = fmaf( qgm[m], stc[m][c], oa[a][c]);
          }
      }
    }
    if (kh) {
      #pragma unroll
      for (int a = 0; a < 4; a++)
        *reinterpret_cast<float4*>(&s.red[kh-1][th][a*4]) =
          make_float4(va[a][0], va[a][1], va[a][2], va[a][3]);
    }
    __syncthreads();  // (3)
    if (!kh) {
      #pragma unroll
      for (int a = 0; a < 4; a++) {
        const int i = r0 + a;
        const float4 u4 = *reinterpret_cast<const float4*>(&s.uu[i][vv]);
        const float4 p0 = *reinterpret_cast<const float4*>(&s.red[0][th][a*4]);
        const float4 p1 = *reinterpret_cast<const float4*>(&s.red[1][th][a*4]);
        const float4 p2 = *reinterpret_cast<const float4*>(&s.red[2][th][a*4]);
        const float wi = s.w[i];
        float4 vq, wq;
        vq.x = u4.x + va[a][0] + p0.x + p1.x + p2.x;
        vq.y = u4.y + va[a][1] + p0.y + p1.y + p2.y;
        vq.z = u4.z + va[a][2] + p0.z + p1.z + p2.z;
        vq.w = u4.w + va[a][3] + p0.w + p1.w + p2.w;
        wq.x = vq.x*wi; wq.y = vq.y*wi; wq.z = vq.z*wi; wq.w = vq.w*wi;
        *reinterpret_cast<float4*>(&s.vn [i][vv]) = vq;
        *reinterpret_cast<float4*>(&s.vnw[i][vv]) = wq;
      }
    }
    __syncthreads();  // (4) vn ready; kc/qg/uu dead

    // ---- A(n+1): kc,qg,uu ----
    if (n + 1 < NCH) {
      const float* gw = g_w  + (rb + CC)*DK;
      const float* gq = g_qg + (rb + CC)*DK;
      #pragma unroll
      for (int rep = 0; rep < 4; rep++) {
        const int idx = t + rep*512;
        const int so = swz(idx >> 5, idx & 31);
        cpa16(&s.kc[so], gw + idx*4);
        cpa16(&s.qg[so], gq + idx*4);
      }
      const int rr = t >> 3, c4 = (t & 7)*4;
      cpa16(&s.uu[rr][c4], g_u + (rb + CC + rr)*DK + v0 + c4);
    }
    cpa_commit();
    cpa_wait<2>();    // B(n) landed: atT
    __syncthreads();  // (4b) publish atT

    // ---- stage C: oa += attn @ vn over j4 = kh, kh+4, ... <= rg ----
    for (int j4 = kh; j4 <= rg; j4 += 4) {
      #pragma unroll
      for (int jj = 0; jj < 4; jj++) {
        const int j = j4*4 + jj;
        const float4 a4 = *reinterpret_cast<const float4*>(&s.atT[j][r0]);
        const float4 v4 = *reinterpret_cast<const float4*>(&s.vn[j][vv]);
        const float am[4] = {a4.x, a4.y, a4.z, a4.w};
        const float vm[4] = {v4.x, v4.y, v4.z, v4.w};
        #pragma unroll
        for (int a = 0; a < 4; a++)
          #pragma unroll
          for (int c = 0; c < 4; c++)
            oa[a][c] = fmaf(am[a], vm[c], oa[a][c]);
      }
    }
    if (kh) {
      #pragma unroll
      for (int a = 0; a < 4; a++)
        *reinterpret_cast<float4*>(&s.red[kh-1][th][a*4]) =
          make_float4(oa[a][0], oa[a][1], oa[a][2], oa[a][3]);
    }
    __syncthreads();  // (5) red-C ready; atT dead

    // ---- B(n+1): atT ----
    if (n + 1 < NCH) {
      const float* ga = g_at + (rb + CC)*CC;
      #pragma unroll
      for (int rep = 0; rep < 2; rep++) {
        const int idx = t + rep*512;
        cpa16(&s.atT[idx >> 4][(idx & 15)*4], ga + idx*4);
      }
    }
    cpa_commit();

    // output store overlaps the C(n) wait
    if (!kh) {
      #pragma unroll
      for (int a = 0; a < 4; a++) {
        const float4 p0 = *reinterpret_cast<const float4*>(&s.red[0][th][a*4]);
        const float4 p1 = *reinterpret_cast<const float4*>(&s.red[1][th][a*4]);
        const float4 p2 = *reinterpret_cast<const float4*>(&s.red[2][th][a*4]);
        float4 o4;
        o4.x = oa[a][0] + p0.x + p1.x + p2.x;
        o4.y = oa[a][1] + p0.y + p1.y + p2.y;
        o4.z = oa[a][2] + p0.z + p1.z + p2.z;
        o4.w = oa[a][3] + p0.w + p1.w + p2.w;
        *reinterpret_cast<float4*>(
            out + ((size_t)(b*Ssz + n*CC + r0 + a)*Hsz + h)*DK + v0 + vv) = o4;
      }
    }
    cpa_wait<2>();    // C(n) landed: kn
    __syncthreads();  // (5b) publish kn

    // ---- stage D: st = el*st + kn^T @ vnw (2 rows x 4 cols, all 512) ----
    {
      float acc[2][4] = {};
      #pragma unroll 4
      for (int i = 0; i < CC; i++) {
        const float2 k2 = *reinterpret_cast<const float2*>(&s.kn[i*DK + d0D]);
        const float4 v4 = *reinterpret_cast<const float4*>(&s.vnw[i][vvD]);
        const float vm[4] = {v4.x, v4.y, v4.z, v4.w};
        #pragma unroll
        for (int c = 0; c < 4; c++) {
          acc[0][c] = fmaf(k2.x, vm[c], acc[0][c]);
          acc[1][c] = fmaf(k2.y, vm[c], acc[1][c]);
        }
      }
      const float el = s.elv;
      #pragma unroll
      for (int a = 0; a < 2; a++) {
        float4 s4 = *reinterpret_cast<const float4*>(&s.st[d0D+a][vvD]);
        s4.x = fmaf(s4.x, el, acc[a][0]);
        s4.y = fmaf(s4.y, el, acc[a][1]);
        s4.z = fmaf(s4.z, el, acc[a][2]);
        s4.w = fmaf(s4.w, el, acc[a][3]);
        *reinterpret_cast<float4*>(&s.st[d0D+a][vvD]) = s4;
      }
    }
  }
}

// ================= launch =================
extern "C" void kernel_launch(void* const* d_in, const int* in_sizes, int n_in,
                              void* d_out, int out_size) {
  const float* q    = (const float*)d_in[0];
  const float* k    = (const float*)d_in[1];
  const float* v    = (const float*)d_in[2];
  const float* g    = (const float*)d_in[3];
  const float* beta = (const float*)d_in[4];
  float* out = (float*)d_out;

  cudaFuncSetAttribute((const void*)phase1_kernel,
                       cudaFuncAttributeMaxDynamicSharedMemorySize, (int)sizeof(P1S));
  cudaFuncSetAttribute((const void*)phase2_kernel,
                       cudaFuncAttributeMaxDynamicSharedMemorySize, (int)sizeof(P2S));

  phase1_kernel<<<BH*NCH, 256, sizeof(P1S)>>>(q, k, v, g, beta);
  phase2_kernel<<<BH*SPLIT, 512, sizeof(P2S)>>>(out);
}

// round 12
// speedup vs baseline: 1.0026x; 1.0026x over previous
#include <cuda_runtime.h>
#include <cuda_bf16.h>
#include <cstdint>

#define Bsz 2
#define Ssz 4096
#define Hsz 16
#define DK  128
#define CC  64
#define NCH (Ssz/CC)      // 64 chunks
#define BH  (Bsz*Hsz)     // 32
#define CCP 68            // phase1 transposed row pad
#define SPLIT 4
#define DVS (DK/SPLIT)    // 32
#define ATP 68            // phase2 attnT row pad
#define VNP 36            // phase2 DVS-wide row pad
#define REDW 20           // reduction row stride

// -------- scratch (device globals: allocation-free rule) --------
__device__ float g_qg[(size_t)BH*Ssz*DK];   // normalized q * Dk^-0.5 * exp(gcs)
__device__ float g_kn[(size_t)BH*Ssz*DK];   // normalized k
__device__ float g_u [(size_t)BH*Ssz*DK];   // Tinv @ (v*beta)
__device__ float g_w [(size_t)BH*Ssz*DK];   // Tinv @ (k*beta*exp(gcs))  (kcd)
__device__ float g_at[(size_t)BH*Ssz*CC];   // intra-chunk attn TRANSPOSED: [j][i]
__device__ float g_gc[(size_t)BH*Ssz];      // within-chunk cumsum of g

// 16B async copy global->shared
__device__ __forceinline__ void cpa16(void* dst, const void* src) {
  unsigned d = (unsigned)__cvta_generic_to_shared(dst);
  asm volatile("cp.async.cg.shared.global [%0], [%1], 16;" :: "r"(d), "l"(src));
}
__device__ __forceinline__ void cpa_commit() {
  asm volatile("cp.async.commit_group;");
}
template<int N> __device__ __forceinline__ void cpa_wait() {
  asm volatile("cp.async.wait_group %0;" :: "n"(N) : "memory");
}

// XOR bank swizzle for kc/qg tiles (row stride 128 floats; c4 in float4 units)
__device__ __forceinline__ int swz(int r, int c4) {
  return (r << 7) + ((c4 ^ ((r >> 2) & 3)) << 2);
}

struct P1S {
  float knT[DK][CCP];
  float qgT[DK][CCP];
  float A  [CC][CC];
  float gcs[CC];
  float bet[CC];
  float eg[CC];
  float er[CC];
  float ebg[CC];
};

struct P2S {
  float st [DK][VNP];      // state slice [DK][DVS]
  float kn [CC*DK];        // stride 128, unswizzled
  float kc [CC*DK];        // swizzled
  float qg [CC*DK];        // swizzled
  float uu [CC][VNP];
  float atT[CC][ATP];      // attn transposed [j][i]
  float vn [CC][VNP];
  float vnw[CC][VNP];      // vn * exp(g_last - gcs_i)
  float red[3][128][REDW]; // split-K partials (quarters 1..3)
  float w  [CC];
  float elv;               // exp(g_last)
};

// ================= Phase 1: per-chunk precompute (grid = BH*NCH) =================
__global__ void __launch_bounds__(256, 2) phase1_kernel(
    const float* __restrict__ q, const float* __restrict__ k,
    const float* __restrict__ v, const float* __restrict__ g,
    const float* __restrict__ beta)
{
  extern __shared__ char smraw[];
  P1S& s = *reinterpret_cast<P1S*>(smraw);
  const int t    = threadIdx.x;
  const int lane = t & 31;
  const int warp = t >> 5;
  const int cid = blockIdx.x;
  const int bh = cid / NCH, n = cid % NCH;
  const int b = bh / Hsz, h = bh % Hsz;
  const int s0 = n * CC;

  if (t < CC) {
    s.bet[t] = beta[(size_t)(b*Ssz + s0 + t)*Hsz + h];
    s.gcs[t] = g   [(size_t)(b*Ssz + s0 + t)*Hsz + h];
  }
  __syncthreads();
  if (t < CC) {
    float x = s.gcs[t];
    #pragma unroll
    for (int o = 1; o < 32; o <<= 1) {
      float y = __shfl_up_sync(0xffffffffu, x, o);
      if (lane >= o) x += y;
    }
    s.gcs[t] = x;
  }
  __syncthreads();
  if (t < CC) {
    float gi = s.gcs[t];
    if (t >= 32) { gi += s.gcs[31]; s.gcs[t] = gi; }
    const float e = __expf(gi);
    s.eg[t]  = e;
    s.er[t]  = __expf(-gi);
    s.ebg[t] = s.bet[t] * e;
    g_gc[(size_t)bh*Ssz + s0 + t] = gi;
  }
  __syncthreads();

  for (int r = warp; r < CC; r += 8) {
    const size_t base = ((size_t)(b*Ssz + s0 + r)*Hsz + h)*DK;
    float kv[4], qv[4];
    float ssk = 0.f, ssq = 0.f;
    #pragma unroll
    for (int i = 0; i < 4; i++) {
      kv[i] = k[base + lane + 32*i]; ssk = fmaf(kv[i], kv[i], ssk);
      qv[i] = q[base + lane + 32*i]; ssq = fmaf(qv[i], qv[i], ssq);
    }
    #pragma unroll
    for (int o = 16; o; o >>= 1) {
      ssk += __shfl_xor_sync(0xffffffffu, ssk, o);
      ssq += __shfl_xor_sync(0xffffffffu, ssq, o);
    }
    const float rk = rsqrtf(ssk + 1e-6f);
    const float rq = rsqrtf(ssq + 1e-6f) * 0.08838834764831845f * s.eg[r];
    const size_t ob = ((size_t)bh*Ssz + s0 + r)*DK;
    #pragma unroll
    for (int i = 0; i < 4; i++) {
      const int d = lane + 32*i;
      const float kk = kv[i]*rk, qq = qv[i]*rq;
      s.knT[d][r] = kk; g_kn[ob + d] = kk;
      s.qgT[d][r] = qq; g_qg[ob + d] = qq;
    }
  }
  __syncthreads();

  // ---- GEMM: A (strict lower) + attn (tril) stored TRANSPOSED ----
  {
    const int ti = t >> 4, tj = t & 15;
    const size_t atb = ((size_t)bh*Ssz + s0)*CC;
    if (tj <= ti) {
      float accA[4][4] = {}, accT[4][4] = {};
      #pragma unroll 4
      for (int d = 0; d < DK; d++) {
        const float4 kd4 = *reinterpret_cast<const float4*>(&s.knT[d][ti*4]);
        const float4 qd4 = *reinterpret_cast<const float4*>(&s.qgT[d][ti*4]);
        const float4 kj4 = *reinterpret_cast<const float4*>(&s.knT[d][tj*4]);
        const float kd[4] = {kd4.x, kd4.y, kd4.z, kd4.w};
        const float qd[4] = {qd4.x, qd4.y, qd4.z, qd4.w};
        const float kj[4] = {kj4.x, kj4.y, kj4.z, kj4.w};
        #pragma unroll
        for (int a = 0; a < 4; a++)
          #pragma unroll
          for (int c = 0; c < 4; c++) {
            accA[a][c] = fmaf(kd[a], kj[c], accA[a][c]);
            accT[a][c] = fmaf(qd[a], kj[c], accT[a][c]);
          }
      }
      const float erj[4] = {s.er[tj*4], s.er[tj*4+1], s.er[tj*4+2], s.er[tj*4+3]};
      #pragma unroll
      for (int a = 0; a < 4; a++) {
        const int i = ti*4 + a;
        const float bei = s.bet[i] * s.eg[i];
        float4 av; float* ap = &av.x;
        #pragma unroll
        for (int c = 0; c < 4; c++) {
          const int j = tj*4 + c;
          ap[c] = (j < i) ? accA[a][c]*bei*erj[c] : 0.f;
        }
        *reinterpret_cast<float4*>(&s.A[i][tj*4]) = av;
      }
      #pragma unroll
      for (int c = 0; c < 4; c++) {
        const int j = tj*4 + c;
        float4 tv; float* tp = &tv.x;
        #pragma unroll
        for (int a = 0; a < 4; a++) {
          const int i = ti*4 + a;
          tp[a] = (j <= i) ? accT[a][c]*erj[c] : 0.f;
        }
        *reinterpret_cast<float4*>(&g_at[atb + (size_t)j*CC + ti*4]) = tv;
      }
    } else {
      const float4 z = {0.f, 0.f, 0.f, 0.f};
      #pragma unroll
      for (int a = 0; a < 4; a++)
        *reinterpret_cast<float4*>(&s.A[ti*4 + a][tj*4]) = z;
      #pragma unroll
      for (int c = 0; c < 4; c++)
        *reinterpret_cast<float4*>(&g_at[atb + (size_t)(tj*4 + c)*CC + ti*4]) = z;
    }
  }
  __syncthreads();

  float xr[CC];
  if (t < DK) {
    #pragma unroll 8
    for (int i = 0; i < CC; i++)
      xr[i] = v[((size_t)(b*Ssz + s0 + i)*Hsz + h)*DK + t] * s.bet[i];
  } else {
    const int d = t - DK;
    #pragma unroll 8
    for (int i = 0; i < CC; i++)
      xr[i] = s.knT[d][i] * s.ebg[i];
  }

  #pragma unroll
  for (int i = 1; i < CC; i++) {
    const float4* Ai = reinterpret_cast<const float4*>(&s.A[i][0]);
    float a0 = 0.f, a1 = 0.f, a2 = 0.f, a3 = 0.f;
    const int nq = (i + 3) >> 2;
    #pragma unroll
    for (int j4 = 0; j4 < nq; j4++) {
      const float4 av = Ai[j4];
      a0 = fmaf(av.x, xr[j4*4+0], a0);
      a1 = fmaf(av.y, xr[j4*4+1], a1);
      a2 = fmaf(av.z, xr[j4*4+2], a2);
      a3 = fmaf(av.w, xr[j4*4+3], a3);
    }
    xr[i] -= (a0 + a1) + (a2 + a3);
  }

  {
    const size_t ob = ((size_t)bh*Ssz + s0)*DK;
    if (t < DK) {
      #pragma unroll 8
      for (int i = 0; i < CC; i++) g_u[ob + (size_t)i*DK + t] = xr[i];
    } else {
      const int d = t - DK;
      #pragma unroll 8
      for (int i = 0; i < CC; i++) g_w[ob + (size_t)i*DK + d] = xr[i];
    }
  }
}

// ===== Phase 2: scan (BH*SPLIT CTAs, 512 thr, 3-group rotating cp.async) =====
__global__ void __launch_bounds__(512, 1) phase2_kernel(float* __restrict__ out)
{
  extern __shared__ char smraw[];
  P2S& s = *reinterpret_cast<P2S*>(smraw);
  const int t  = threadIdx.x;
  const int bh = blockIdx.x / SPLIT;
  const int sp = blockIdx.x % SPLIT;
  const int b = bh / Hsz, h = bh % Hsz;
  const int v0 = sp * DVS;

  for (int i = t; i < DK*VNP; i += 512) (&s.st[0][0])[i] = 0.f;

  const int kh = t >> 7;        // d-quarter / split phase (0..3)
  const int th = t & 127;
  const int rg = th >> 3;       // 16 row groups (stages B/C)
  const int rgl = rg & 3;       // per-thread swizzle key
  const int r0 = rg * 4;
  const int vv = (th & 7) * 4;  // 4 cols
  const int d0D = (t >> 3) * 2; // stage D: 64 d-groups x 2 rows
  const int vvD = (t & 7) * 4;

  const size_t cb = (size_t)bh*Ssz;

  // ---- prologue: A(0) = {kc,qg,uu},  B(0) = {atT} ----
  {
    const float* gw = g_w  + cb*DK;
    const float* gq = g_qg + cb*DK;
    #pragma unroll
    for (int rep = 0; rep < 4; rep++) {
      const int idx = t + rep*512;
      const int so = swz(idx >> 5, idx & 31);
      cpa16(&s.kc[so], gw + idx*4);
      cpa16(&s.qg[so], gq + idx*4);
    }
    { const int rr = t >> 3, c4 = (t & 7)*4;
      cpa16(&s.uu[rr][c4], g_u + (cb + rr)*DK + v0 + c4); }
    cpa_commit();                                   // A(0)
    #pragma unroll
    for (int rep = 0; rep < 2; rep++) {
      const int idx = t + rep*512;
      cpa16(&s.atT[idx >> 4][(idx & 15)*4], g_at + cb*CC + idx*4);
    }
    cpa_commit();                                   // B(0)
  }

  for (int n = 0; n < NCH; n++) {
    const size_t rb = cb + n*CC;
    __syncthreads();  // (1) prev-chunk stage D done: kn buffer free

    // ---- C(n): kn(n) ----
    {
      const float* gk = g_kn + rb*DK;
      #pragma unroll
      for (int rep = 0; rep < 4; rep++) {
        const int idx = t + rep*512;
        cpa16(&s.kn[idx*4], gk + idx*4);
      }
      cpa_commit();
    }
    cpa_wait<2>();    // A(n) landed: kc/qg/uu
    __syncthreads();  // (2) publish
    if (t < CC) {
      const float gl = g_gc[rb + CC - 1];
      s.w[t] = __expf(gl - g_gc[rb + t]);
      if (t == CC-1) s.elv = __expf(gl);
    }

    // ---- stage B: va = -kc@st ; oa = qg@st  (quarter kh: 32 d's) ----
    float va[4][4] = {}, oa[4][4] = {};
    #pragma unroll 2
    for (int d4 = 0; d4 < 8; d4++) {
      const int c4b = kh*8 + d4;
      const int d = c4b*4;
      const int co = (c4b ^ rgl) << 2;   // swizzled column offset (floats)
      float stc[4][4];
      #pragma unroll
      for (int m = 0; m < 4; m++) {
        const float4 s4 = *reinterpret_cast<const float4*>(&s.st[d+m][vv]);
        stc[m][0]=s4.x; stc[m][1]=s4.y; stc[m][2]=s4.z; stc[m][3]=s4.w;
      }
      #pragma unroll
      for (int a = 0; a < 4; a++) {
        const int ofs = ((r0+a) << 7) + co;
        const float4 kc4 = *reinterpret_cast<const float4*>(&s.kc[ofs]);
        const float4 qg4 = *reinterpret_cast<const float4*>(&s.qg[ofs]);
        const float kcm[4] = {kc4.x, kc4.y, kc4.z, kc4.w};
        const float qgm[4] = {qg4.x, qg4.y, qg4.z, qg4.w};
        #pragma unroll
        for (int m = 0; m < 4; m++)
          #pragma unroll
          for (int c = 0; c < 4; c++) {
            va[a][c] = fmaf(-kcm[m], stc[m][c], va[a][c]);
            oa[a][c] = fmaf( qgm[m], stc[m][c], oa[a][c]);
          }
      }
    }
    if (kh) {
      #pragma unroll
      for (int a = 0; a < 4; a++)
        *reinterpret_cast<float4*>(&s.red[kh-1][th][a*4]) =
          make_float4(va[a][0], va[a][1], va[a][2], va[a][3]);
    }
    __syncthreads();  // (3)
    if (!kh) {
      #pragma unroll
      for (int a = 0; a < 4; a++) {
        const int i = r0 + a;
        const float4 u4 = *reinterpret_cast<const float4*>(&s.uu[i][vv]);
        const float4 p0 = *reinterpret_cast<const float4*>(&s.red[0][th][a*4]);
        const float4 p1 = *reinterpret_cast<const float4*>(&s.red[1][th][a*4]);
        const float4 p2 = *reinterpret_cast<const float4*>(&s.red[2][th][a*4]);
        const float wi = s.w[i];
        float4 vq, wq;
        vq.x = u4.x + va[a][0] + p0.x + p1.x + p2.x;
        vq.y = u4.y + va[a][1] + p0.y + p1.y + p2.y;
        vq.z = u4.z + va[a][2] + p0.z + p1.z + p2.z;
        vq.w = u4.w + va[a][3] + p0.w + p1.w + p2.w;
        wq.x = vq.x*wi; wq.y = vq.y*wi; wq.z = vq.z*wi; wq.w = vq.w*wi;
        *reinterpret_cast<float4*>(&s.vn [i][vv]) = vq;
        *reinterpret_cast<float4*>(&s.vnw[i][vv]) = wq;
      }
    }
    __syncthreads();  // (4) vn ready; kc/qg/uu dead

    // ---- A(n+1): kc,qg,uu ----
    if (n + 1 < NCH) {
      const float* gw = g_w  + (rb + CC)*DK;
      const float* gq = g_qg + (rb + CC)*DK;
      #pragma unroll
      for (int rep = 0; rep < 4; rep++) {
        const int idx = t + rep*512;
        const int so = swz(idx >> 5, idx & 31);
        cpa16(&s.kc[so], gw + idx*4);
        cpa16(&s.qg[so], gq + idx*4);
      }
      const int rr = t >> 3, c4 = (t & 7)*4;
      cpa16(&s.uu[rr][c4], g_u + (rb + CC + rr)*DK + v0 + c4);
    }
    cpa_commit();
    cpa_wait<2>();    // B(n) landed: atT
    __syncthreads();  // (4b) publish atT

    // ---- stage C: oa += attn @ vn over j4 = kh, kh+4, ... <= rg ----
    for (int j4 = kh; j4 <= rg; j4 += 4) {
      #pragma unroll
      for (int jj = 0; jj < 4; jj++) {
        const int j = j4*4 + jj;
        const float4 a4 = *reinterpret_cast<const float4*>(&s.atT[j][r0]);
        const float4 v4 = *reinterpret_cast<const float4*>(&s.vn[j][vv]);
        const float am[4] = {a4.x, a4.y, a4.z, a4.w};
        const float vm[4] = {v4.x, v4.y, v4.z, v4.w};
        #pragma unroll
        for (int a = 0; a < 4; a++)
          #pragma unroll
          for (int c = 0; c < 4; c++)
            oa[a][c] = fmaf(am[a], vm[c], oa[a][c]);
      }
    }
    if (kh) {
      #pragma unroll
      for (int a = 0; a < 4; a++)
        *reinterpret_cast<float4*>(&s.red[kh-1][th][a*4]) =
          make_float4(oa[a][0], oa[a][1], oa[a][2], oa[a][3]);
    }
    __syncthreads();  // (5) red-C ready; atT dead

    // ---- B(n+1): atT ----
    if (n + 1 < NCH) {
      const float* ga = g_at + (rb + CC)*CC;
      #pragma unroll
      for (int rep = 0; rep < 2; rep++) {
        const int idx = t + rep*512;
        cpa16(&s.atT[idx >> 4][(idx & 15)*4], ga + idx*4);
      }
    }
    cpa_commit();

    // output store overlaps the C(n) wait
    if (!kh) {
      #pragma unroll
      for (int a = 0; a < 4; a++) {
        const float4 p0 = *reinterpret_cast<const float4*>(&s.red[0][th][a*4]);
        const float4 p1 = *reinterpret_cast<const float4*>(&s.red[1][th][a*4]);
        const float4 p2 = *reinterpret_cast<const float4*>(&s.red[2][th][a*4]);
        float4 o4;
        o4.x = oa[a][0] + p0.x + p1.x + p2.x;
        o4.y = oa[a][1] + p0.y + p1.y + p2.y;
        o4.z = oa[a][2] + p0.z + p1.z + p2.z;
        o4.w = oa[a][3] + p0.w + p1.w + p2.w;
        *reinterpret_cast<float4*>(
            out + ((size_t)(b*Ssz + n*CC + r0 + a)*Hsz + h)*DK + v0 + vv) = o4;
      }
    }
    cpa_wait<2>();    // C(n) landed: kn
    __syncthreads();  // (5b) publish kn

    // ---- stage D: st = el*st + kn^T @ vnw (2 rows x 4 cols, all 512) ----
    {
      float acc[2][4] = {};
      #pragma unroll 4
      for (int i = 0; i < CC; i++) {
        const float2 k2 = *reinterpret_cast<const float2*>(&s.kn[i*DK + d0D]);
        const float4 v4 = *reinterpret_cast<const float4*>(&s.vnw[i][vvD]);
        const float vm[4] = {v4.x, v4.y, v4.z, v4.w};
        #pragma unroll
        for (int c = 0; c < 4; c++) {
          acc[0][c] = fmaf(k2.x, vm[c], acc[0][c]);
          acc[1][c] = fmaf(k2.y, vm[c], acc[1][c]);
        }
      }
      const float el = s.elv;
      #pragma unroll
      for (int a = 0; a < 2; a++) {
        float4 s4 = *reinterpret_cast<const float4*>(&s.st[d0D+a][vvD]);
        s4.x = fmaf(s4.x, el, acc[a][0]);
        s4.y = fmaf(s4.y, el, acc[a][1]);
        s4.z = fmaf(s4.z, el, acc[a][2]);
        s4.w = fmaf(s4.w, el, acc[a][3]);
        *reinterpret_cast<float4*>(&s.st[d0D+a][vvD]) = s4;
      }
    }
  }
}

// ================= launch =================
extern "C" void kernel_launch(void* const* d_in, const int* in_sizes, int n_in,
                              void* d_out, int out_size) {
  const float* q    = (const float*)d_in[0];
  const float* k    = (const float*)d_in[1];
  const float* v    = (const float*)d_in[2];
  const float* g    = (const float*)d_in[3];
  const float* beta = (const float*)d_in[4];
  float* out = (float*)d_out;

  cudaFuncSetAttribute((const void*)phase1_kernel,
                       cudaFuncAttributeMaxDynamicSharedMemorySize, (int)sizeof(P1S));
  cudaFuncSetAttribute((const void*)phase2_kernel,
                       cudaFuncAttributeMaxDynamicSharedMemorySize, (int)sizeof(P2S));

  phase1_kernel<<<BH*NCH, 256, sizeof(P1S)>>>(q, k, v, g, beta);
  phase2_kernel<<<BH*SPLIT, 512, sizeof(P2S)>>>(out);
}

// round 14
// speedup vs baseline: 1.0076x; 1.0050x over previous
#include <cuda_runtime.h>
#include <cuda_bf16.h>
#include <mma.h>
#include <cstdint>

#define Bsz 2
#define Ssz 4096
#define Hsz 16
#define DK  128
#define CC  64
#define NCH (Ssz/CC)
#define BH  (Bsz*Hsz)
#define SPLIT 4
#define DVS (DK/SPLIT)
#define ATP 68
#define VNP 36
#define REDW 20
#define DST 68            // phase1 D row stride (floats)
#define CTS 136           // phase1 bf16 tile row stride (elements)

// ---- phase1 smem byte offsets ----
#define CT_HI 0           // bf16 [128][136]  rows 0-63 = k, 64-127 = qg
#define CT_LO 34816       // bf16 lo tile
#define P1_D  69632       // float [128][68]  (GEMM result, then scaled in place)
#define P1_SC 104448      // 5 x 64 floats
#define P1_BYTES 105728

// -------- scratch (device globals) --------
__device__ float g_qg[(size_t)BH*Ssz*DK];
__device__ float g_kn[(size_t)BH*Ssz*DK];
__device__ float g_u [(size_t)BH*Ssz*DK];
__device__ float g_w [(size_t)BH*Ssz*DK];
__device__ float g_at[(size_t)BH*Ssz*CC];   // attn TRANSPOSED [j][i]
__device__ float g_gc[(size_t)BH*Ssz];

__device__ __forceinline__ void cpa16(void* dst, const void* src) {
  unsigned d = (unsigned)__cvta_generic_to_shared(dst);
  asm volatile("cp.async.cg.shared.global [%0], [%1], 16;" :: "r"(d), "l"(src));
}
__device__ __forceinline__ void cpa_commit() { asm volatile("cp.async.commit_group;"); }
template<int N> __device__ __forceinline__ void cpa_wait() {
  asm volatile("cp.async.wait_group %0;" :: "n"(N) : "memory");
}
__device__ __forceinline__ int swz(int r, int c4) {
  return (r << 7) + ((c4 ^ ((r >> 2) & 3)) << 2);
}

struct P2S {
  float st [DK][VNP];
  float kn [CC*DK];
  float kc [CC*DK];
  float qg [CC*DK];
  float uu [CC][VNP];
  float atT[CC][ATP];
  float vn [CC][VNP];
  float vnw[CC][VNP];
  float red[3][128][REDW];
  float w  [CC];
  float elv;
};

// ================= Phase 1 (grid = BH*NCH, 256 thr, WMMA bf16 GEMM) =================
__global__ void __launch_bounds__(256, 2) phase1_kernel(
    const float* __restrict__ q, const float* __restrict__ k,
    const float* __restrict__ v, const float* __restrict__ g,
    const float* __restrict__ beta)
{
  using namespace nvcuda;
  extern __shared__ __align__(16) char sm[];
  __nv_bfloat16* ctHi = (__nv_bfloat16*)(sm + CT_HI);
  __nv_bfloat16* ctLo = (__nv_bfloat16*)(sm + CT_LO);
  float* sD    = (float*)(sm + P1_D);
  float* s_gcs = (float*)(sm + P1_SC);
  float* s_bet = s_gcs + 64;
  float* s_eg  = s_bet + 64;
  float* s_er  = s_eg  + 64;
  float* s_ebg = s_er  + 64;

  const int t    = threadIdx.x;
  const int lane = t & 31;
  const int warp = t >> 5;
  const int cid = blockIdx.x;
  const int bh = cid / NCH, n = cid % NCH;
  const int b = bh / Hsz, h = bh % Hsz;
  const int s0 = n * CC;

  // ---- g,beta load + inclusive scan + exponentials ----
  if (t < CC) {
    s_bet[t] = beta[(size_t)(b*Ssz + s0 + t)*Hsz + h];
    s_gcs[t] = g   [(size_t)(b*Ssz + s0 + t)*Hsz + h];
  }
  __syncthreads();
  if (t < CC) {
    float x = s_gcs[t];
    #pragma unroll
    for (int o = 1; o < 32; o <<= 1) {
      float y = __shfl_up_sync(0xffffffffu, x, o);
      if (lane >= o) x += y;
    }
    s_gcs[t] = x;
  }
  __syncthreads();
  if (t < CC) {
    float gi = s_gcs[t];
    if (t >= 32) { gi += s_gcs[31]; s_gcs[t] = gi; }
    const float e = __expf(gi);
    s_eg[t]  = e;
    s_er[t]  = __expf(-gi);
    s_ebg[t] = s_bet[t] * e;
    g_gc[(size_t)bh*Ssz + s0 + t] = gi;
  }
  __syncthreads();

  // ---- normalize; write fp32 globals + bf16 hi/lo stacked tile ----
  for (int r = warp; r < CC; r += 8) {
    const size_t base = ((size_t)(b*Ssz + s0 + r)*Hsz + h)*DK;
    float kv[4], qv[4];
    float ssk = 0.f, ssq = 0.f;
    #pragma unroll
    for (int i = 0; i < 4; i++) {
      kv[i] = k[base + lane + 32*i]; ssk = fmaf(kv[i], kv[i], ssk);
      qv[i] = q[base + lane + 32*i]; ssq = fmaf(qv[i], qv[i], ssq);
    }
    #pragma unroll
    for (int o = 16; o; o >>= 1) {
      ssk += __shfl_xor_sync(0xffffffffu, ssk, o);
      ssq += __shfl_xor_sync(0xffffffffu, ssq, o);
    }
    const float rk = rsqrtf(ssk + 1e-6f);
    const float rq = rsqrtf(ssq + 1e-6f) * 0.08838834764831845f * s_eg[r];
    const size_t ob = ((size_t)bh*Ssz + s0 + r)*DK;
    #pragma unroll
    for (int i = 0; i < 4; i++) {
      const int d = lane + 32*i;
      const float kk = kv[i]*rk, qq = qv[i]*rq;
      g_kn[ob + d] = kk; g_qg[ob + d] = qq;
      const __nv_bfloat16 khv = __float2bfloat16(kk);
      const __nv_bfloat16 klv = __float2bfloat16(kk - __bfloat162float(khv));
      const __nv_bfloat16 qhv = __float2bfloat16(qq);
      const __nv_bfloat16 qlv = __float2bfloat16(qq - __bfloat162float(qhv));
      ctHi[r*CTS + d]        = khv;
      ctLo[r*CTS + d]        = klv;
      ctHi[(r + 64)*CTS + d] = qhv;
      ctLo[(r + 64)*CTS + d] = qlv;
    }
  }
  __syncthreads();

  // ---- WMMA GEMM: D[128,64] = [k;qg] @ k^T, 3-term bf16 split ----
  // 8 warps x 16-row slabs; triangular tile skip: warp needs n-tiles 0..(warp&3)
  {
    const int wl = warp & 3;
    wmma::fragment<wmma::accumulator, 16, 16, 16, float> acc[4];
    #pragma unroll
    for (int nt = 0; nt < 4; nt++)
      if (nt <= wl) wmma::fill_fragment(acc[nt], 0.f);
    const __nv_bfloat16* Ab[3] = {ctHi, ctHi, ctLo};
    const __nv_bfloat16* Bb[3] = {ctHi, ctLo, ctHi};
    #pragma unroll 1
    for (int p = 0; p < 3; p++) {
      #pragma unroll 1
      for (int ks = 0; ks < 8; ks++) {
        wmma::fragment<wmma::matrix_a, 16, 16, 16, __nv_bfloat16, wmma::row_major> af;
        wmma::load_matrix_sync(af, Ab[p] + warp*16*CTS + ks*16, CTS);
        #pragma unroll
        for (int nt = 0; nt < 4; nt++) {
          if (nt <= wl) {
            wmma::fragment<wmma::matrix_b, 16, 16, 16, __nv_bfloat16, wmma::col_major> bf;
            wmma::load_matrix_sync(bf, Bb[p] + nt*16*CTS + ks*16, CTS);
            wmma::mma_sync(acc[nt], af, bf, acc[nt]);
          }
        }
      }
    }
    #pragma unroll
    for (int nt = 0; nt < 4; nt++)
      if (nt <= wl)
        wmma::store_matrix_sync(sD + warp*16*DST + nt*16, acc[nt], DST, wmma::mem_row_major);
  }
  __syncthreads();

  // ---- epilogue: scale + mask in place (rows 0-63 -> A, 64-127 -> attn) ----
  {
    const int row = t >> 1, jb = (t & 1) * 32;
    const bool isA = row < 64;
    const int i = isA ? row : row - 64;
    const float rsc = isA ? s_bet[i] * s_eg[i] : 1.f;
    #pragma unroll
    for (int j4 = 0; j4 < 8; j4++) {
      const int j0 = jb + j4*4;
      const float4 d4 = *(const float4*)&sD[row*DST + j0];
      const float4 er4 = *(const float4*)&s_er[j0];
      const float dm[4] = {d4.x, d4.y, d4.z, d4.w};
      const float em[4] = {er4.x, er4.y, er4.z, er4.w};
      float4 o; float* op = &o.x;
      #pragma unroll
      for (int c = 0; c < 4; c++) {
        const int j = j0 + c;
        const bool keep = isA ? (j < i) : (j <= i);
        op[c] = keep ? dm[c] * em[c] * rsc : 0.f;
      }
      *(float4*)&sD[row*DST + j0] = o;
    }
  }
  __syncthreads();

  // ---- transpose attn (rows 64-127) -> g_at[j][i] ----
  {
    const int j = t & 63, qi = t >> 6;
    const size_t atb = ((size_t)bh*Ssz + s0)*CC + (size_t)j*CC + qi*16;
    #pragma unroll
    for (int q4 = 0; q4 < 4; q4++) {
      float4 o;
      o.x = sD[(64 + qi*16 + q4*4 + 0)*DST + j];
      o.y = sD[(64 + qi*16 + q4*4 + 1)*DST + j];
      o.z = sD[(64 + qi*16 + q4*4 + 2)*DST + j];
      o.w = sD[(64 + qi*16 + q4*4 + 3)*DST + j];
      *(float4*)&g_at[atb + q4*4] = o;
    }
  }

  // ---- x init: column t of [v*beta | kn*beta*e^gcs] ----
  float xr[CC];
  if (t < DK) {
    #pragma unroll 8
    for (int i = 0; i < CC; i++)
      xr[i] = v[((size_t)(b*Ssz + s0 + i)*Hsz + h)*DK + t] * s_bet[i];
  } else {
    const int d = t - DK;
    const size_t ob = ((size_t)bh*Ssz + s0)*DK;
    #pragma unroll 8
    for (int i = 0; i < CC; i++)
      xr[i] = g_kn[ob + (size_t)i*DK + d] * s_ebg[i];
  }

  // ---- forward substitution: (I+A) x' = x  (A = sD rows 0-63) ----
  #pragma unroll
  for (int i = 1; i < CC; i++) {
    const float4* Ai = (const float4*)&sD[i*DST];
    float a0 = 0.f, a1 = 0.f, a2 = 0.f, a3 = 0.f;
    const int nq = (i + 3) >> 2;
    #pragma unroll
    for (int j4 = 0; j4 < nq; j4++) {
      const float4 av = Ai[j4];
      a0 = fmaf(av.x, xr[j4*4+0], a0);
      a1 = fmaf(av.y, xr[j4*4+1], a1);
      a2 = fmaf(av.z, xr[j4*4+2], a2);
      a3 = fmaf(av.w, xr[j4*4+3], a3);
    }
    xr[i] -= (a0 + a1) + (a2 + a3);
  }

  {
    const size_t ob = ((size_t)bh*Ssz + s0)*DK;
    if (t < DK) {
      #pragma unroll 8
      for (int i = 0; i < CC; i++) g_u[ob + (size_t)i*DK + t] = xr[i];
    } else {
      const int d = t - DK;
      #pragma unroll 8
      for (int i = 0; i < CC; i++) g_w[ob + (size_t)i*DK + d] = xr[i];
    }
  }
}

// ===== Phase 2: scan (BH*SPLIT CTAs, 512 thr, 3-group rotating cp.async) =====
__global__ void __launch_bounds__(512, 1) phase2_kernel(float* __restrict__ out)
{
  extern __shared__ char smraw[];
  P2S& s = *reinterpret_cast<P2S*>(smraw);
  const int t  = threadIdx.x;
  const int bh = blockIdx.x / SPLIT;
  const int sp = blockIdx.x % SPLIT;
  const int b = bh / Hsz, h = bh % Hsz;
  const int v0 = sp * DVS;

  for (int i = t; i < DK*VNP; i += 512) (&s.st[0][0])[i] = 0.f;

  const int kh = t >> 7;
  const int th = t & 127;
  const int rg = th >> 3;
  const int rgl = rg & 3;
  const int r0 = rg * 4;
  const int vv = (th & 7) * 4;
  const int d0D = (t >> 3) * 2;
  const int vvD = (t & 7) * 4;

  const size_t cb = (size_t)bh*Ssz;

  {
    const float* gw = g_w  + cb*DK;
    const float* gq = g_qg + cb*DK;
    #pragma unroll
    for (int rep = 0; rep < 4; rep++) {
      const int idx = t + rep*512;
      const int so = swz(idx >> 5, idx & 31);
      cpa16(&s.kc[so], gw + idx*4);
      cpa16(&s.qg[so], gq + idx*4);
    }
    { const int rr = t >> 3, c4 = (t & 7)*4;
      cpa16(&s.uu[rr][c4], g_u + (cb + rr)*DK + v0 + c4); }
    cpa_commit();
    #pragma unroll
    for (int rep = 0; rep < 2; rep++) {
      const int idx = t + rep*512;
      cpa16(&s.atT[idx >> 4][(idx & 15)*4], g_at + cb*CC + idx*4);
    }
    cpa_commit();
  }

  for (int n = 0; n < NCH; n++) {
    const size_t rb = cb + n*CC;
    __syncthreads();  // (1)

    {
      const float* gk = g_kn + rb*DK;
      #pragma unroll
      for (int rep = 0; rep < 4; rep++) {
        const int idx = t + rep*512;
        cpa16(&s.kn[idx*4], gk + idx*4);
      }
      cpa_commit();
    }
    cpa_wait<2>();
    __syncthreads();  // (2)
    if (t < CC) {
      const float gl = g_gc[rb + CC - 1];
      s.w[t] = __expf(gl - g_gc[rb + t]);
      if (t == CC-1) s.elv = __expf(gl);
    }

    float va[4][4] = {}, oa[4][4] = {};
    #pragma unroll 2
    for (int d4 = 0; d4 < 8; d4++) {
      const int c4b = kh*8 + d4;
      const int d = c4b*4;
      const int co = (c4b ^ rgl) << 2;
      float stc[4][4];
      #pragma unroll
      for (int m = 0; m < 4; m++) {
        const float4 s4 = *reinterpret_cast<const float4*>(&s.st[d+m][vv]);
        stc[m][0]=s4.x; stc[m][1]=s4.y; stc[m][2]=s4.z; stc[m][3]=s4.w;
      }
      #pragma unroll
      for (int a = 0; a < 4; a++) {
        const int ofs = ((r0+a) << 7) + co;
        const float4 kc4 = *reinterpret_cast<const float4*>(&s.kc[ofs]);
        const float4 qg4 = *reinterpret_cast<const float4*>(&s.qg[ofs]);
        const float kcm[4] = {kc4.x, kc4.y, kc4.z, kc4.w};
        const float qgm[4] = {qg4.x, qg4.y, qg4.z, qg4.w};
        #pragma unroll
        for (int m = 0; m < 4; m++)
          #pragma unroll
          for (int c = 0; c < 4; c++) {
            va[a][c] = fmaf(-kcm[m], stc[m][c], va[a][c]);
            oa[a][c] = fmaf( qgm[m], stc[m][c], oa[a][c]);
          }
      }
    }
    if (kh) {
      #pragma unroll
      for (int a = 0; a < 4; a++)
        *reinterpret_cast<float4*>(&s.red[kh-1][th][a*4]) =
          make_float4(va[a][0], va[a][1], va[a][2], va[a][3]);
    }
    __syncthreads();  // (3)
    if (!kh) {
      #pragma unroll
      for (int a = 0; a < 4; a++) {
        const int i = r0 + a;
        const float4 u4 = *reinterpret_cast<const float4*>(&s.uu[i][vv]);
        const float4 p0 = *reinterpret_cast<const float4*>(&s.red[0][th][a*4]);
        const float4 p1 = *reinterpret_cast<const float4*>(&s.red[1][th][a*4]);
        const float4 p2 = *reinterpret_cast<const float4*>(&s.red[2][th][a*4]);
        const float wi = s.w[i];
        float4 vq, wq;
        vq.x = u4.x + va[a][0] + p0.x + p1.x + p2.x;
        vq.y = u4.y + va[a][1] + p0.y + p1.y + p2.y;
        vq.z = u4.z + va[a][2] + p0.z + p1.z + p2.z;
        vq.w = u4.w + va[a][3] + p0.w + p1.w + p2.w;
        wq.x = vq.x*wi; wq.y = vq.y*wi; wq.z = vq.z*wi; wq.w = vq.w*wi;
        *reinterpret_cast<float4*>(&s.vn [i][vv]) = vq;
        *reinterpret_cast<float4*>(&s.vnw[i][vv]) = wq;
      }
    }
    __syncthreads();  // (4)

    if (n + 1 < NCH) {
      const float* gw = g_w  + (rb + CC)*DK;
      const float* gq = g_qg + (rb + CC)*DK;
      #pragma unroll
      for (int rep = 0; rep < 4; rep++) {
        const int idx = t + rep*512;
        const int so = swz(idx >> 5, idx & 31);
        cpa16(&s.kc[so], gw + idx*4);
        cpa16(&s.qg[so], gq + idx*4);
      }
      const int rr = t >> 3, c4 = (t & 7)*4;
      cpa16(&s.uu[rr][c4], g_u + (rb + CC + rr)*DK + v0 + c4);
    }
    cpa_commit();
    cpa_wait<2>();
    __syncthreads();  // (4b)

    for (int j4 = kh; j4 <= rg; j4 += 4) {
      #pragma unroll
      for (int jj = 0; jj < 4; jj++) {
        const int j = j4*4 + jj;
        const float4 a4 = *reinterpret_cast<const float4*>(&s.atT[j][r0]);
        const float4 v4 = *reinterpret_cast<const float4*>(&s.vn[j][vv]);
        const float am[4] = {a4.x, a4.y, a4.z, a4.w};
        const float vm[4] = {v4.x, v4.y, v4.z, v4.w};
        #pragma unroll
        for (int a = 0; a < 4; a++)
          #pragma unroll
          for (int c = 0; c < 4; c++)
            oa[a][c] = fmaf(am[a], vm[c], oa[a][c]);
      }
    }
    if (kh) {
      #pragma unroll
      for (int a = 0; a < 4; a++)
        *reinterpret_cast<float4*>(&s.red[kh-1][th][a*4]) =
          make_float4(oa[a][0], oa[a][1], oa[a][2], oa[a][3]);
    }
    __syncthreads();  // (5)

    if (n + 1 < NCH) {
      const float* ga = g_at + (rb + CC)*CC;
      #pragma unroll
      for (int rep = 0; rep < 2; rep++) {
        const int idx = t + rep*512;
        cpa16(&s.atT[idx >> 4][(idx & 15)*4], ga + idx*4);
      }
    }
    cpa_commit();

    if (!kh) {
      #pragma unroll
      for (int a = 0; a < 4; a++) {
        const float4 p0 = *reinterpret_cast<const float4*>(&s.red[0][th][a*4]);
        const float4 p1 = *reinterpret_cast<const float4*>(&s.red[1][th][a*4]);
        const float4 p2 = *reinterpret_cast<const float4*>(&s.red[2][th][a*4]);
        float4 o4;
        o4.x = oa[a][0] + p0.x + p1.x + p2.x;
        o4.y = oa[a][1] + p0.y + p1.y + p2.y;
        o4.z = oa[a][2] + p0.z + p1.z + p2.z;
        o4.w = oa[a][3] + p0.w + p1.w + p2.w;
        *reinterpret_cast<float4*>(
            out + ((size_t)(b*Ssz + n*CC + r0 + a)*Hsz + h)*DK + v0 + vv) = o4;
      }
    }
    cpa_wait<2>();
    __syncthreads();  // (5b)

    {
      float acc[2][4] = {};
      #pragma unroll 4
      for (int i = 0; i < CC; i++) {
        const float2 k2 = *reinterpret_cast<const float2*>(&s.kn[i*DK + d0D]);
        const float4 v4 = *reinterpret_cast<const float4*>(&s.vnw[i][vvD]);
        const float vm[4] = {v4.x, v4.y, v4.z, v4.w};
        #pragma unroll
        for (int c = 0; c < 4; c++) {
          acc[0][c] = fmaf(k2.x, vm[c], acc[0][c]);
          acc[1][c] = fmaf(k2.y, vm[c], acc[1][c]);
        }
      }
      const float el = s.elv;
      #pragma unroll
      for (int a = 0; a < 2; a++) {
        float4 s4 = *reinterpret_cast<const float4*>(&s.st[d0D+a][vvD]);
        s4.x = fmaf(s4.x, el, acc[a][0]);
        s4.y = fmaf(s4.y, el, acc[a][1]);
        s4.z = fmaf(s4.z, el, acc[a][2]);
        s4.w = fmaf(s4.w, el, acc[a][3]);
        *reinterpret_cast<float4*>(&s.st[d0D+a][vvD]) = s4;
      }
    }
  }
}

// ================= launch =================
extern "C" void kernel_launch(void* const* d_in, const int* in_sizes, int n_in,
                              void* d_out, int out_size) {
  const float* q    = (const float*)d_in[0];
  const float* k    = (const float*)d_in[1];
  const float* v    = (const float*)d_in[2];
  const float* g    = (const float*)d_in[3];
  const float* beta = (const float*)d_in[4];
  float* out = (float*)d_out;

  cudaFuncSetAttribute((const void*)phase1_kernel,
                       cudaFuncAttributeMaxDynamicSharedMemorySize, P1_BYTES);
  cudaFuncSetAttribute((const void*)phase2_kernel,
                       cudaFuncAttributeMaxDynamicSharedMemorySize, (int)sizeof(P2S));

  phase1_kernel<<<BH*NCH, 256, P1_BYTES>>>(q, k, v, g, beta);
  phase2_kernel<<<BH*SPLIT, 512, sizeof(P2S)>>>(out);
}

// round 16
// speedup vs baseline: 1.1540x; 1.1453x over previous
#include <cuda_runtime.h>
#include <cuda_bf16.h>
#include <mma.h>
#include <cstdint>

#define Bsz 2
#define Ssz 4096
#define Hsz 16
#define DK  128
#define CC  64
#define NCH (Ssz/CC)
#define BH  (Bsz*Hsz)
#define SPLIT 4
#define DVS (DK/SPLIT)
#define DST 68            // phase1 D row stride (floats)
#define CTS 136           // bf16 tile row stride (elements)

// ---- phase1 smem byte offsets ----
#define CT_HI 0           // bf16 [128][136]  rows 0-63 = k, 64-127 = qg
#define CT_LO 34816
#define P1_D  69632       // float [128][68]
#define P1_SC 104448      // 5 x 64 floats
#define P1_BYTES 105728

// -------- scratch (device globals) --------
__device__ __nv_bfloat16 g_knH[(size_t)BH*Ssz*DK];
__device__ __nv_bfloat16 g_knL[(size_t)BH*Ssz*DK];
__device__ __nv_bfloat16 g_qgH[(size_t)BH*Ssz*DK];
__device__ __nv_bfloat16 g_qgL[(size_t)BH*Ssz*DK];
__device__ __nv_bfloat16 g_kcH[(size_t)BH*Ssz*DK];
__device__ __nv_bfloat16 g_kcL[(size_t)BH*Ssz*DK];
__device__ float g_u [(size_t)BH*Ssz*DK];
__device__ float g_at[(size_t)BH*Ssz*CC];   // attn TRANSPOSED [j][i], fp32
__device__ float g_gc[(size_t)BH*Ssz];

__device__ __forceinline__ void cpa16(void* dst, const void* src) {
  unsigned d = (unsigned)__cvta_generic_to_shared(dst);
  asm volatile("cp.async.cg.shared.global [%0], [%1], 16;" :: "r"(d), "l"(src));
}
__device__ __forceinline__ void cpa_commit() { asm volatile("cp.async.commit_group;"); }
template<int N> __device__ __forceinline__ void cpa_wait() {
  asm volatile("cp.async.wait_group %0;" :: "n"(N) : "memory");
}

// ================= Phase 2 shared struct =================
struct P2S {
  float stF[32][132];            // state TRANSPOSED [v][d], fp32 master
  __nv_bfloat16 stH[32][136];    // state bf16 hi (col-major B operand view)
  __nv_bfloat16 stL[32][136];
  __nv_bfloat16 kcH[CC][CTS];
  __nv_bfloat16 kcL[CC][CTS];
  __nv_bfloat16 qgH[CC][CTS];
  __nv_bfloat16 qgL[CC][CTS];
  __nv_bfloat16 knH[CC][CTS];
  __nv_bfloat16 knL[CC][CTS];
  __nv_bfloat16 vwH[32][72];     // vnw TRANSPOSED [v][i] hi
  __nv_bfloat16 vwL[32][72];
  float uu [CC][36];
  float atT[CC][68];
  float vn [CC][36];             // va (fragment store) then vn in place
  float oaS[CC][36];
  float w  [CC];
  float elv;
};

// ================= Phase 1 (grid = BH*NCH, 256 thr, WMMA bf16 GEMM) =================
__global__ void __launch_bounds__(256, 2) phase1_kernel(
    const float* __restrict__ q, const float* __restrict__ k,
    const float* __restrict__ v, const float* __restrict__ g,
    const float* __restrict__ beta)
{
  using namespace nvcuda;
  extern __shared__ __align__(16) char sm[];
  __nv_bfloat16* ctHi = (__nv_bfloat16*)(sm + CT_HI);
  __nv_bfloat16* ctLo = (__nv_bfloat16*)(sm + CT_LO);
  float* sD    = (float*)(sm + P1_D);
  float* s_gcs = (float*)(sm + P1_SC);
  float* s_bet = s_gcs + 64;
  float* s_eg  = s_bet + 64;
  float* s_er  = s_eg  + 64;
  float* s_ebg = s_er  + 64;

  const int t    = threadIdx.x;
  const int lane = t & 31;
  const int warp = t >> 5;
  const int cid = blockIdx.x;
  const int bh = cid / NCH, n = cid % NCH;
  const int b = bh / Hsz, h = bh % Hsz;
  const int s0 = n * CC;

  if (t < CC) {
    s_bet[t] = beta[(size_t)(b*Ssz + s0 + t)*Hsz + h];
    s_gcs[t] = g   [(size_t)(b*Ssz + s0 + t)*Hsz + h];
  }
  __syncthreads();
  if (t < CC) {
    float x = s_gcs[t];
    #pragma unroll
    for (int o = 1; o < 32; o <<= 1) {
      float y = __shfl_up_sync(0xffffffffu, x, o);
      if (lane >= o) x += y;
    }
    s_gcs[t] = x;
  }
  __syncthreads();
  if (t < CC) {
    float gi = s_gcs[t];
    if (t >= 32) { gi += s_gcs[31]; s_gcs[t] = gi; }
    const float e = __expf(gi);
    s_eg[t]  = e;
    s_er[t]  = __expf(-gi);
    s_ebg[t] = s_bet[t] * e;
    g_gc[(size_t)bh*Ssz + s0 + t] = gi;
  }
  __syncthreads();

  // ---- normalize; bf16 hi/lo -> smem tiles + kn/qg bf16 globals ----
  for (int r = warp; r < CC; r += 8) {
    const size_t base = ((size_t)(b*Ssz + s0 + r)*Hsz + h)*DK;
    float kv[4], qv[4];
    float ssk = 0.f, ssq = 0.f;
    #pragma unroll
    for (int i = 0; i < 4; i++) {
      kv[i] = k[base + lane + 32*i]; ssk = fmaf(kv[i], kv[i], ssk);
      qv[i] = q[base + lane + 32*i]; ssq = fmaf(qv[i], qv[i], ssq);
    }
    #pragma unroll
    for (int o = 16; o; o >>= 1) {
      ssk += __shfl_xor_sync(0xffffffffu, ssk, o);
      ssq += __shfl_xor_sync(0xffffffffu, ssq, o);
    }
    const float rk = rsqrtf(ssk + 1e-6f);
    const float rq = rsqrtf(ssq + 1e-6f) * 0.08838834764831845f * s_eg[r];
    const size_t ob = ((size_t)bh*Ssz + s0 + r)*DK;
    #pragma unroll
    for (int i = 0; i < 4; i++) {
      const int d = lane + 32*i;
      const float kk = kv[i]*rk, qq = qv[i]*rq;
      const __nv_bfloat16 khv = __float2bfloat16(kk);
      const __nv_bfloat16 klv = __float2bfloat16(kk - __bfloat162float(khv));
      const __nv_bfloat16 qhv = __float2bfloat16(qq);
      const __nv_bfloat16 qlv = __float2bfloat16(qq - __bfloat162float(qhv));
      ctHi[r*CTS + d]        = khv;
      ctLo[r*CTS + d]        = klv;
      ctHi[(r + 64)*CTS + d] = qhv;
      ctLo[(r + 64)*CTS + d] = qlv;
      g_knH[ob + d] = khv; g_knL[ob + d] = klv;
      g_qgH[ob + d] = qhv; g_qgL[ob + d] = qlv;
    }
  }
  __syncthreads();

  // ---- WMMA GEMM: D[128,64] = [k;qg] @ k^T, 3-term bf16 split ----
  {
    const int wl = warp & 3;
    wmma::fragment<wmma::accumulator, 16, 16, 16, float> acc[4];
    #pragma unroll
    for (int nt = 0; nt < 4; nt++)
      if (nt <= wl) wmma::fill_fragment(acc[nt], 0.f);
    const __nv_bfloat16* Ab[3] = {ctHi, ctHi, ctLo};
    const __nv_bfloat16* Bb[3] = {ctHi, ctLo, ctHi};
    #pragma unroll 1
    for (int p = 0; p < 3; p++) {
      #pragma unroll 1
      for (int ks = 0; ks < 8; ks++) {
        wmma::fragment<wmma::matrix_a, 16, 16, 16, __nv_bfloat16, wmma::row_major> af;
        wmma::load_matrix_sync(af, Ab[p] + warp*16*CTS + ks*16, CTS);
        #pragma unroll
        for (int nt = 0; nt < 4; nt++) {
          if (nt <= wl) {
            wmma::fragment<wmma::matrix_b, 16, 16, 16, __nv_bfloat16, wmma::col_major> bf;
            wmma::load_matrix_sync(bf, Bb[p] + nt*16*CTS + ks*16, CTS);
            wmma::mma_sync(acc[nt], af, bf, acc[nt]);
          }
        }
      }
    }
    #pragma unroll
    for (int nt = 0; nt < 4; nt++)
      if (nt <= wl)
        wmma::store_matrix_sync(sD + warp*16*DST + nt*16, acc[nt], DST, wmma::mem_row_major);
  }
  __syncthreads();

  // ---- epilogue: scale + mask in place ----
  {
    const int row = t >> 1, jb = (t & 1) * 32;
    const bool isA = row < 64;
    const int i = isA ? row : row - 64;
    const float rsc = isA ? s_bet[i] * s_eg[i] : 1.f;
    #pragma unroll
    for (int j4 = 0; j4 < 8; j4++) {
      const int j0 = jb + j4*4;
      const float4 d4 = *(const float4*)&sD[row*DST + j0];
      const float4 er4 = *(const float4*)&s_er[j0];
      const float dm[4] = {d4.x, d4.y, d4.z, d4.w};
      const float em[4] = {er4.x, er4.y, er4.z, er4.w};
      float4 o; float* op = &o.x;
      #pragma unroll
      for (int c = 0; c < 4; c++) {
        const int j = j0 + c;
        const bool keep = isA ? (j < i) : (j <= i);
        op[c] = keep ? dm[c] * em[c] * rsc : 0.f;
      }
      *(float4*)&sD[row*DST + j0] = o;
    }
  }
  __syncthreads();

  // ---- transpose attn (rows 64-127) -> g_at[j][i] ----
  {
    const int j = t & 63, qi = t >> 6;
    const size_t atb = ((size_t)bh*Ssz + s0)*CC + (size_t)j*CC + qi*16;
    #pragma unroll
    for (int q4 = 0; q4 < 4; q4++) {
      float4 o;
      o.x = sD[(64 + qi*16 + q4*4 + 0)*DST + j];
      o.y = sD[(64 + qi*16 + q4*4 + 1)*DST + j];
      o.z = sD[(64 + qi*16 + q4*4 + 2)*DST + j];
      o.w = sD[(64 + qi*16 + q4*4 + 3)*DST + j];
      *(float4*)&g_at[atb + q4*4] = o;
    }
  }

  // ---- x init: column t of [v*beta | kn*beta*e^gcs] ----
  float xr[CC];
  if (t < DK) {
    #pragma unroll 8
    for (int i = 0; i < CC; i++)
      xr[i] = v[((size_t)(b*Ssz + s0 + i)*Hsz + h)*DK + t] * s_bet[i];
  } else {
    const int d = t - DK;
    #pragma unroll 4
    for (int i = 0; i < CC; i++) {
      const float kk = __bfloat162float(ctHi[i*CTS + d])
                     + __bfloat162float(ctLo[i*CTS + d]);
      xr[i] = kk * s_ebg[i];
    }
  }

  // ---- forward substitution: (I+A) x' = x ----
  #pragma unroll
  for (int i = 1; i < CC; i++) {
    const float4* Ai = (const float4*)&sD[i*DST];
    float a0 = 0.f, a1 = 0.f, a2 = 0.f, a3 = 0.f;
    const int nq = (i + 3) >> 2;
    #pragma unroll
    for (int j4 = 0; j4 < nq; j4++) {
      const float4 av = Ai[j4];
      a0 = fmaf(av.x, xr[j4*4+0], a0);
      a1 = fmaf(av.y, xr[j4*4+1], a1);
      a2 = fmaf(av.z, xr[j4*4+2], a2);
      a3 = fmaf(av.w, xr[j4*4+3], a3);
    }
    xr[i] -= (a0 + a1) + (a2 + a3);
  }

  {
    const size_t ob = ((size_t)bh*Ssz + s0)*DK;
    if (t < DK) {
      #pragma unroll 8
      for (int i = 0; i < CC; i++) g_u[ob + (size_t)i*DK + t] = xr[i];
    } else {
      const int d = t - DK;
      #pragma unroll 4
      for (int i = 0; i < CC; i++) {
        const float val = xr[i];
        const __nv_bfloat16 hi = __float2bfloat16(val);
        const __nv_bfloat16 lo = __float2bfloat16(val - __bfloat162float(hi));
        g_kcH[ob + (size_t)i*DK + d] = hi;
        g_kcL[ob + (size_t)i*DK + d] = lo;
      }
    }
  }
}

// ===== Phase 2: scan (BH*SPLIT CTAs, 256 thr, WMMA stages B/D) =====
__global__ void __launch_bounds__(256, 1) phase2_kernel(float* __restrict__ out)
{
  using namespace nvcuda;
  extern __shared__ __align__(16) char smraw[];
  P2S& s = *reinterpret_cast<P2S*>(smraw);
  const int t  = threadIdx.x;
  const int warp = t >> 5;
  const int bh = blockIdx.x / SPLIT;
  const int sp = blockIdx.x % SPLIT;
  const int b = bh / Hsz, h = bh % Hsz;
  const int v0 = sp * DVS;

  // zero stF + stH + stL (contiguous at struct head)
  {
    const int zn = (int)((sizeof(s.stF) + sizeof(s.stH) + sizeof(s.stL)) / 4);
    int* zp = (int*)&s.stF[0][0];
    for (int i = t; i < zn; i += 256) zp[i] = 0;
  }

  const int rg = t >> 4;        // 16 row groups (scalar stages)
  const int cg = t & 15;        // 16 col groups
  const int r0 = rg * 4;
  const int vv = cg * 2;
  const int wmi = warp >> 1;    // stage B m tile (0..3)
  const int wni = warp & 1;     // stage B n tile (0..1)
  const int dmi = warp >> 2;    // stage D m tile (0..1)
  const int cvr = t & 31;       // convert: row
  const int cvc = (t >> 5)*16;  // convert: col base

  const size_t cb = (size_t)bh*Ssz;

  // ---- prologue: A(0) = {kc,qg,uu},  B(0) = {atT} ----
  {
    const size_t rb = cb;
    #pragma unroll
    for (int idx = t; idx < 1024; idx += 256) {
      const int row = idx >> 4, c16 = (idx & 15)*8;
      const size_t go = (rb + row)*DK + c16;
      cpa16(&s.kcH[row][c16], g_kcH + go);
      cpa16(&s.kcL[row][c16], g_kcL + go);
      cpa16(&s.qgH[row][c16], g_qgH + go);
      cpa16(&s.qgL[row][c16], g_qgL + go);
    }
    #pragma unroll
    for (int idx = t; idx < 512; idx += 256) {
      const int row = idx >> 3, c4 = (idx & 7)*4;
      cpa16(&s.uu[row][c4], g_u + (rb + row)*DK + v0 + c4);
    }
    cpa_commit();
    #pragma unroll
    for (int idx = t; idx < 1024; idx += 256) {
      const int row = idx >> 4, c4 = (idx & 15)*4;
      cpa16(&s.atT[row][c4], g_at + rb*CC + (size_t)row*CC + c4);
    }
    cpa_commit();
  }

  for (int n = 0; n < NCH; n++) {
    const size_t rb = cb + n*CC;
    __syncthreads();  // (1) prev-chunk D + convert done; kn buffer free

    // ---- C(n): kn hi/lo ----
    #pragma unroll
    for (int idx = t; idx < 1024; idx += 256) {
      const int row = idx >> 4, c16 = (idx & 15)*8;
      const size_t go = (rb + row)*DK + c16;
      cpa16(&s.knH[row][c16], g_knH + go);
      cpa16(&s.knL[row][c16], g_knL + go);
    }
    cpa_commit();
    cpa_wait<2>();    // A(n): kc/qg/uu landed
    __syncthreads();  // (2)
    if (t < CC) {
      const float gl = g_gc[rb + CC - 1];
      s.w[t] = __expf(gl - g_gc[rb + t]);
      if (t == CC-1) s.elv = __expf(gl);
    }

    // ---- stage B (WMMA): va = kc@stT^T ; oa = qg@stT^T ----
    {
      wmma::fragment<wmma::accumulator, 16, 16, 16, float> accV, accO;
      wmma::fill_fragment(accV, 0.f);
      wmma::fill_fragment(accO, 0.f);
      #pragma unroll 1
      for (int ks = 0; ks < 8; ks++) {
        wmma::fragment<wmma::matrix_a, 16, 16, 16, __nv_bfloat16, wmma::row_major> aH, aL, qH, qL;
        wmma::fragment<wmma::matrix_b, 16, 16, 16, __nv_bfloat16, wmma::col_major> bH, bL;
        wmma::load_matrix_sync(aH, &s.kcH[wmi*16][ks*16], CTS);
        wmma::load_matrix_sync(aL, &s.kcL[wmi*16][ks*16], CTS);
        wmma::load_matrix_sync(qH, &s.qgH[wmi*16][ks*16], CTS);
        wmma::load_matrix_sync(qL, &s.qgL[wmi*16][ks*16], CTS);
        wmma::load_matrix_sync(bH, &s.stH[wni*16][ks*16], 136);
        wmma::load_matrix_sync(bL, &s.stL[wni*16][ks*16], 136);
        wmma::mma_sync(accV, aH, bH, accV);
        wmma::mma_sync(accO, qH, bH, accO);
        wmma::mma_sync(accV, aH, bL, accV);
        wmma::mma_sync(accO, qH, bL, accO);
        wmma::mma_sync(accV, aL, bH, accV);
        wmma::mma_sync(accO, qL, bH, accO);
      }
      wmma::store_matrix_sync(&s.vn [wmi*16][wni*16], accV, 36, wmma::mem_row_major);
      wmma::store_matrix_sync(&s.oaS[wmi*16][wni*16], accO, 36, wmma::mem_row_major);
    }
    __syncthreads();  // (3)

    // ---- scalar epilogue: vn = uu - va ; vnwT bf16 hi/lo ----
    {
      #pragma unroll
      for (int a = 0; a < 4; a++) {
        const int i = r0 + a;
        const float2 u2 = *(const float2*)&s.uu[i][vv];
        const float2 va2 = *(const float2*)&s.vn[i][vv];
        float2 v2; v2.x = u2.x - va2.x; v2.y = u2.y - va2.y;
        *(float2*)&s.vn[i][vv] = v2;
        const float wi = s.w[i];
        const float w0 = v2.x * wi, w1 = v2.y * wi;
        const __nv_bfloat16 h0 = __float2bfloat16(w0);
        const __nv_bfloat16 h1 = __float2bfloat16(w1);
        s.vwH[vv  ][i] = h0; s.vwL[vv  ][i] = __float2bfloat16(w0 - __bfloat162float(h0));
        s.vwH[vv+1][i] = h1; s.vwL[vv+1][i] = __float2bfloat16(w1 - __bfloat162float(h1));
      }
    }
    __syncthreads();  // (4) kc/qg/uu dead

    // ---- A(n+1): kc,qg,uu ----
    if (n + 1 < NCH) {
      const size_t rb1 = rb + CC;
      #pragma unroll
      for (int idx = t; idx < 1024; idx += 256) {
        const int row = idx >> 4, c16 = (idx & 15)*8;
        const size_t go = (rb1 + row)*DK + c16;
        cpa16(&s.kcH[row][c16], g_kcH + go);
        cpa16(&s.kcL[row][c16], g_kcL + go);
        cpa16(&s.qgH[row][c16], g_qgH + go);
        cpa16(&s.qgL[row][c16], g_qgL + go);
      }
      #pragma unroll
      for (int idx = t; idx < 512; idx += 256) {
        const int row = idx >> 3, c4 = (idx & 7)*4;
        cpa16(&s.uu[row][c4], g_u + (rb1 + row)*DK + v0 + c4);
      }
    }
    cpa_commit();
    cpa_wait<2>();    // B(n): atT landed
    __syncthreads();  // (4b)

    // ---- stage C (scalar, triangular): o = oaS + attn @ vn ; store ----
    {
      float oa[4][2];
      #pragma unroll
      for (int a = 0; a < 4; a++) {
        const float2 o2 = *(const float2*)&s.oaS[r0+a][vv];
        oa[a][0] = o2.x; oa[a][1] = o2.y;
      }
      for (int j4 = 0; j4 <= rg; j4++) {
        #pragma unroll
        for (int jj = 0; jj < 4; jj++) {
          const int j = j4*4 + jj;
          const float4 a4 = *(const float4*)&s.atT[j][r0];
          const float2 v2 = *(const float2*)&s.vn[j][vv];
          const float am[4] = {a4.x, a4.y, a4.z, a4.w};
          #pragma unroll
          for (int a = 0; a < 4; a++) {
            oa[a][0] = fmaf(am[a], v2.x, oa[a][0]);
            oa[a][1] = fmaf(am[a], v2.y, oa[a][1]);
          }
        }
      }
      #pragma unroll
      for (int a = 0; a < 4; a++) {
        float2 o2; o2.x = oa[a][0]; o2.y = oa[a][1];
        *(float2*)(out + ((size_t)(b*Ssz + n*CC + r0 + a)*Hsz + h)*DK + v0 + vv) = o2;
      }
    }
    __syncthreads();  // (5) atT dead

    // ---- B(n+1): atT ----
    if (n + 1 < NCH) {
      const size_t rb1 = rb + CC;
      #pragma unroll
      for (int idx = t; idx < 1024; idx += 256) {
        const int row = idx >> 4, c4 = (idx & 15)*4;
        cpa16(&s.atT[row][c4], g_at + rb1*CC + (size_t)row*CC + c4);
      }
    }
    cpa_commit();
    cpa_wait<2>();    // C(n): kn landed
    __syncthreads();  // (5b)

    // ---- stage D (WMMA): stT = el*stT + vnwT @ kn ----
    {
      const float el = s.elv;
      const int ni0 = (warp & 3)*2;
      wmma::fragment<wmma::accumulator, 16, 16, 16, float> accD[2];
      #pragma unroll
      for (int sub = 0; sub < 2; sub++) {
        wmma::load_matrix_sync(accD[sub], &s.stF[dmi*16][(ni0+sub)*16], 132, wmma::mem_row_major);
        #pragma unroll
        for (int e = 0; e < accD[sub].num_elements; e++) accD[sub].x[e] *= el;
      }
      #pragma unroll 1
      for (int ks = 0; ks < 4; ks++) {
        wmma::fragment<wmma::matrix_a, 16, 16, 16, __nv_bfloat16, wmma::row_major> aH, aL;
        wmma::load_matrix_sync(aH, &s.vwH[dmi*16][ks*16], 72);
        wmma::load_matrix_sync(aL, &s.vwL[dmi*16][ks*16], 72);
        #pragma unroll
        for (int sub = 0; sub < 2; sub++) {
          wmma::fragment<wmma::matrix_b, 16, 16, 16, __nv_bfloat16, wmma::row_major> bH, bL;
          wmma::load_matrix_sync(bH, &s.knH[ks*16][(ni0+sub)*16], CTS);
          wmma::load_matrix_sync(bL, &s.knL[ks*16][(ni0+sub)*16], CTS);
          wmma::mma_sync(accD[sub], aH, bH, accD[sub]);
          wmma::mma_sync(accD[sub], aH, bL, accD[sub]);
          wmma::mma_sync(accD[sub], aL, bH, accD[sub]);
        }
      }
      #pragma unroll
      for (int sub = 0; sub < 2; sub++)
        wmma::store_matrix_sync(&s.stF[dmi*16][(ni0+sub)*16], accD[sub], 132, wmma::mem_row_major);
    }
    __syncthreads();  // (6)

    // ---- convert stF -> stH/stL (bf16 hi/lo) ----
    {
      #pragma unroll
      for (int c = 0; c < 16; c += 4) {
        const float4 f = *(const float4*)&s.stF[cvr][cvc + c];
        const float fm[4] = {f.x, f.y, f.z, f.w};
        #pragma unroll
        for (int e = 0; e < 4; e++) {
          const __nv_bfloat16 hi = __float2bfloat16(fm[e]);
          s.stH[cvr][cvc + c + e] = hi;
          s.stL[cvr][cvc + c + e] = __float2bfloat16(fm[e] - __bfloat162float(hi));
        }
      }
    }
  }
}

// ================= launch =================
extern "C" void kernel_launch(void* const* d_in, const int* in_sizes, int n_in,
                              void* d_out, int out_size) {
  const float* q    = (const float*)d_in[0];
  const float* k    = (const float*)d_in[1];
  const float* v    = (const float*)d_in[2];
  const float* g    = (const float*)d_in[3];
  const float* beta = (const float*)d_in[4];
  float* out = (float*)d_out;

  cudaFuncSetAttribute((const void*)phase1_kernel,
                       cudaFuncAttributeMaxDynamicSharedMemorySize, P1_BYTES);
  cudaFuncSetAttribute((const void*)phase2_kernel,
                       cudaFuncAttributeMaxDynamicSharedMemorySize, (int)sizeof(P2S));

  phase1_kernel<<<BH*NCH, 256, P1_BYTES>>>(q, k, v, g, beta);
  phase2_kernel<<<BH*SPLIT, 256, sizeof(P2S)>>>(out);
}

// round 17
// speedup vs baseline: 1.2395x; 1.0740x over previous
#include <cuda_runtime.h>
#include <cuda_bf16.h>
#include <mma.h>
#include <cstdint>

#define Bsz 2
#define Ssz 4096
#define Hsz 16
#define DK  128
#define CC  64
#define NCH (Ssz/CC)
#define BH  (Bsz*Hsz)
#define SPLIT 4
#define DVS (DK/SPLIT)
#define DST 68            // phase1 D row stride (floats)
#define CTS 136           // bf16 tile row stride (elements)
#define ATS 72            // attn bf16 row stride
#define VNS 40            // vn bf16 row stride

// ---- phase1 smem byte offsets ----
#define CT_HI 0           // bf16 [128][136]  rows 0-63 = k, 64-127 = qg
#define CT_LO 34816
#define P1_D  69632       // float [128][68]
#define P1_SC 104448      // 5 x 64 floats
#define P1_BYTES 105728

// -------- scratch (device globals) --------
__device__ __nv_bfloat16 g_knH[(size_t)BH*Ssz*DK];
__device__ __nv_bfloat16 g_knL[(size_t)BH*Ssz*DK];
__device__ __nv_bfloat16 g_qgH[(size_t)BH*Ssz*DK];
__device__ __nv_bfloat16 g_qgL[(size_t)BH*Ssz*DK];
__device__ __nv_bfloat16 g_kcH[(size_t)BH*Ssz*DK];
__device__ __nv_bfloat16 g_kcL[(size_t)BH*Ssz*DK];
__device__ __nv_bfloat16 g_atH[(size_t)BH*Ssz*CC];  // attn [i][j] bf16 hi
__device__ __nv_bfloat16 g_atL[(size_t)BH*Ssz*CC];  // attn [i][j] bf16 lo
__device__ float g_u [(size_t)BH*Ssz*DK];
__device__ float g_gc[(size_t)BH*Ssz];

__device__ __forceinline__ void cpa16(void* dst, const void* src) {
  unsigned d = (unsigned)__cvta_generic_to_shared(dst);
  asm volatile("cp.async.cg.shared.global [%0], [%1], 16;" :: "r"(d), "l"(src));
}
__device__ __forceinline__ void cpa_commit() { asm volatile("cp.async.commit_group;"); }
template<int N> __device__ __forceinline__ void cpa_wait() {
  asm volatile("cp.async.wait_group %0;" :: "n"(N) : "memory");
}

// ================= Phase 2 shared struct =================
struct P2S {
  float stF[32][132];            // state TRANSPOSED [v][d], fp32 master
  __nv_bfloat16 stH[32][136];    // state bf16 hi (col-major B view)
  __nv_bfloat16 stL[32][136];
  __nv_bfloat16 kcH[CC][CTS];
  __nv_bfloat16 kcL[CC][CTS];
  __nv_bfloat16 qgH[CC][CTS];
  __nv_bfloat16 qgL[CC][CTS];
  __nv_bfloat16 knH[CC][CTS];
  __nv_bfloat16 knL[CC][CTS];
  __nv_bfloat16 atH[CC][ATS];    // attn [i][j] bf16 hi
  __nv_bfloat16 atL[CC][ATS];
  __nv_bfloat16 vnH[CC][VNS];    // vn [j][v] bf16 hi (stage C B operand)
  __nv_bfloat16 vnL[CC][VNS];
  __nv_bfloat16 vwH[32][72];     // vnw TRANSPOSED [v][i] hi
  __nv_bfloat16 vwL[32][72];
  float uu [CC][36];
  float vn [CC][36];             // va (stage B accV store) then read by epilogue
  float w  [CC];
  float elv;
};

// ================= Phase 1 (grid = BH*NCH, 256 thr, WMMA bf16 GEMM) =================
__global__ void __launch_bounds__(256, 2) phase1_kernel(
    const float* __restrict__ q, const float* __restrict__ k,
    const float* __restrict__ v, const float* __restrict__ g,
    const float* __restrict__ beta)
{
  using namespace nvcuda;
  extern __shared__ __align__(16) char sm[];
  __nv_bfloat16* ctHi = (__nv_bfloat16*)(sm + CT_HI);
  __nv_bfloat16* ctLo = (__nv_bfloat16*)(sm + CT_LO);
  float* sD    = (float*)(sm + P1_D);
  float* s_gcs = (float*)(sm + P1_SC);
  float* s_bet = s_gcs + 64;
  float* s_eg  = s_bet + 64;
  float* s_er  = s_eg  + 64;
  float* s_ebg = s_er  + 64;

  const int t    = threadIdx.x;
  const int lane = t & 31;
  const int warp = t >> 5;
  const int cid = blockIdx.x;
  const int bh = cid / NCH, n = cid % NCH;
  const int b = bh / Hsz, h = bh % Hsz;
  const int s0 = n * CC;

  if (t < CC) {
    s_bet[t] = beta[(size_t)(b*Ssz + s0 + t)*Hsz + h];
    s_gcs[t] = g   [(size_t)(b*Ssz + s0 + t)*Hsz + h];
  }
  __syncthreads();
  if (t < CC) {
    float x = s_gcs[t];
    #pragma unroll
    for (int o = 1; o < 32; o <<= 1) {
      float y = __shfl_up_sync(0xffffffffu, x, o);
      if (lane >= o) x += y;
    }
    s_gcs[t] = x;
  }
  __syncthreads();
  if (t < CC) {
    float gi = s_gcs[t];
    if (t >= 32) { gi += s_gcs[31]; s_gcs[t] = gi; }
    const float e = __expf(gi);
    s_eg[t]  = e;
    s_er[t]  = __expf(-gi);
    s_ebg[t] = s_bet[t] * e;
    g_gc[(size_t)bh*Ssz + s0 + t] = gi;
  }
  __syncthreads();

  // ---- normalize; bf16 hi/lo -> smem tiles + kn/qg bf16 globals ----
  for (int r = warp; r < CC; r += 8) {
    const size_t base = ((size_t)(b*Ssz + s0 + r)*Hsz + h)*DK;
    float kv[4], qv[4];
    float ssk = 0.f, ssq = 0.f;
    #pragma unroll
    for (int i = 0; i < 4; i++) {
      kv[i] = k[base + lane + 32*i]; ssk = fmaf(kv[i], kv[i], ssk);
      qv[i] = q[base + lane + 32*i]; ssq = fmaf(qv[i], qv[i], ssq);
    }
    #pragma unroll
    for (int o = 16; o; o >>= 1) {
      ssk += __shfl_xor_sync(0xffffffffu, ssk, o);
      ssq += __shfl_xor_sync(0xffffffffu, ssq, o);
    }
    const float rk = rsqrtf(ssk + 1e-6f);
    const float rq = rsqrtf(ssq + 1e-6f) * 0.08838834764831845f * s_eg[r];
    const size_t ob = ((size_t)bh*Ssz + s0 + r)*DK;
    #pragma unroll
    for (int i = 0; i < 4; i++) {
      const int d = lane + 32*i;
      const float kk = kv[i]*rk, qq = qv[i]*rq;
      const __nv_bfloat16 khv = __float2bfloat16(kk);
      const __nv_bfloat16 klv = __float2bfloat16(kk - __bfloat162float(khv));
      const __nv_bfloat16 qhv = __float2bfloat16(qq);
      const __nv_bfloat16 qlv = __float2bfloat16(qq - __bfloat162float(qhv));
      ctHi[r*CTS + d]        = khv;
      ctLo[r*CTS + d]        = klv;
      ctHi[(r + 64)*CTS + d] = qhv;
      ctLo[(r + 64)*CTS + d] = qlv;
      g_knH[ob + d] = khv; g_knL[ob + d] = klv;
      g_qgH[ob + d] = qhv; g_qgL[ob + d] = qlv;
    }
  }
  __syncthreads();

  // ---- WMMA GEMM: D[128,64] = [k;qg] @ k^T, 3-term bf16 split ----
  {
    const int wl = warp & 3;
    wmma::fragment<wmma::accumulator, 16, 16, 16, float> acc[4];
    #pragma unroll
    for (int nt = 0; nt < 4; nt++)
      if (nt <= wl) wmma::fill_fragment(acc[nt], 0.f);
    const __nv_bfloat16* Ab[3] = {ctHi, ctHi, ctLo};
    const __nv_bfloat16* Bb[3] = {ctHi, ctLo, ctHi};
    #pragma unroll 1
    for (int p = 0; p < 3; p++) {
      #pragma unroll 1
      for (int ks = 0; ks < 8; ks++) {
        wmma::fragment<wmma::matrix_a, 16, 16, 16, __nv_bfloat16, wmma::row_major> af;
        wmma::load_matrix_sync(af, Ab[p] + warp*16*CTS + ks*16, CTS);
        #pragma unroll
        for (int nt = 0; nt < 4; nt++) {
          if (nt <= wl) {
            wmma::fragment<wmma::matrix_b, 16, 16, 16, __nv_bfloat16, wmma::col_major> bf;
            wmma::load_matrix_sync(bf, Bb[p] + nt*16*CTS + ks*16, CTS);
            wmma::mma_sync(acc[nt], af, bf, acc[nt]);
          }
        }
      }
    }
    #pragma unroll
    for (int nt = 0; nt < 4; nt++)
      if (nt <= wl)
        wmma::store_matrix_sync(sD + warp*16*DST + nt*16, acc[nt], DST, wmma::mem_row_major);
  }
  __syncthreads();

  // ---- epilogue: scale + mask; A rows -> sD, attn rows -> g_atH/L bf16 ----
  {
    const int row = t >> 1, jb = (t & 1) * 32;
    const bool isA = row < 64;
    const int i = isA ? row : row - 64;
    const float rsc = isA ? s_bet[i] * s_eg[i] : 1.f;
    const size_t atb = ((size_t)bh*Ssz + s0 + i)*CC;
    #pragma unroll
    for (int j4 = 0; j4 < 8; j4++) {
      const int j0 = jb + j4*4;
      const float4 d4 = *(const float4*)&sD[row*DST + j0];
      const float4 er4 = *(const float4*)&s_er[j0];
      const float dm[4] = {d4.x, d4.y, d4.z, d4.w};
      const float em[4] = {er4.x, er4.y, er4.z, er4.w};
      if (isA) {
        float4 o; float* op = &o.x;
        #pragma unroll
        for (int c = 0; c < 4; c++) {
          const int j = j0 + c;
          op[c] = (j < i) ? dm[c] * em[c] * rsc : 0.f;
        }
        *(float4*)&sD[row*DST + j0] = o;
      } else {
        __nv_bfloat16 hi4[4], lo4[4];
        #pragma unroll
        for (int c = 0; c < 4; c++) {
          const int j = j0 + c;
          const float x = (j <= i) ? dm[c] * em[c] : 0.f;
          hi4[c] = __float2bfloat16(x);
          lo4[c] = __float2bfloat16(x - __bfloat162float(hi4[c]));
        }
        *(unsigned long long*)&g_atH[atb + j0] = *(const unsigned long long*)hi4;
        *(unsigned long long*)&g_atL[atb + j0] = *(const unsigned long long*)lo4;
      }
    }
  }
  __syncthreads();

  // ---- x init: column t of [v*beta | kn*beta*e^gcs] ----
  float xr[CC];
  if (t < DK) {
    #pragma unroll 8
    for (int i = 0; i < CC; i++)
      xr[i] = v[((size_t)(b*Ssz + s0 + i)*Hsz + h)*DK + t] * s_bet[i];
  } else {
    const int d = t - DK;
    #pragma unroll 4
    for (int i = 0; i < CC; i++) {
      const float kk = __bfloat162float(ctHi[i*CTS + d])
                     + __bfloat162float(ctLo[i*CTS + d]);
      xr[i] = kk * s_ebg[i];
    }
  }

  // ---- forward substitution: (I+A) x' = x ----
  #pragma unroll
  for (int i = 1; i < CC; i++) {
    const float4* Ai = (const float4*)&sD[i*DST];
    float a0 = 0.f, a1 = 0.f, a2 = 0.f, a3 = 0.f;
    const int nq = (i + 3) >> 2;
    #pragma unroll
    for (int j4 = 0; j4 < nq; j4++) {
      const float4 av = Ai[j4];
      a0 = fmaf(av.x, xr[j4*4+0], a0);
      a1 = fmaf(av.y, xr[j4*4+1], a1);
      a2 = fmaf(av.z, xr[j4*4+2], a2);
      a3 = fmaf(av.w, xr[j4*4+3], a3);
    }
    xr[i] -= (a0 + a1) + (a2 + a3);
  }

  {
    const size_t ob = ((size_t)bh*Ssz + s0)*DK;
    if (t < DK) {
      #pragma unroll 8
      for (int i = 0; i < CC; i++) g_u[ob + (size_t)i*DK + t] = xr[i];
    } else {
      const int d = t - DK;
      #pragma unroll 4
      for (int i = 0; i < CC; i++) {
        const float val = xr[i];
        const __nv_bfloat16 hi = __float2bfloat16(val);
        const __nv_bfloat16 lo = __float2bfloat16(val - __bfloat162float(hi));
        g_kcH[ob + (size_t)i*DK + d] = hi;
        g_kcL[ob + (size_t)i*DK + d] = lo;
      }
    }
  }
}

// ===== Phase 2: scan (BH*SPLIT CTAs, 256 thr, WMMA stages B/C/D) =====
__global__ void __launch_bounds__(256, 1) phase2_kernel(float* __restrict__ out)
{
  using namespace nvcuda;
  extern __shared__ __align__(16) char smraw[];
  P2S& s = *reinterpret_cast<P2S*>(smraw);
  const int t  = threadIdx.x;
  const int warp = t >> 5;
  const int bh = blockIdx.x / SPLIT;
  const int sp = blockIdx.x % SPLIT;
  const int b = bh / Hsz, h = bh % Hsz;
  const int v0 = sp * DVS;

  // zero stF + stH + stL (contiguous at struct head)
  {
    const int zn = (int)((sizeof(s.stF) + sizeof(s.stH) + sizeof(s.stL)) / 4);
    int* zp = (int*)&s.stF[0][0];
    for (int i = t; i < zn; i += 256) zp[i] = 0;
  }

  const int rg = t >> 4;        // 16 row groups (epilogue)
  const int cg = t & 15;
  const int r0 = rg * 4;
  const int vv = cg * 2;
  const int wmi = warp >> 1;    // stage B/C m tile (0..3)
  const int wni = warp & 1;     // stage B/C n tile (0..1)
  const int dmi = warp >> 2;    // stage D m tile (0..1)
  const int cvr = t & 31;       // convert: row
  const int cvc = (t >> 5)*16;  // convert: col base

  const size_t cb = (size_t)bh*Ssz;

  // ---- prologue: A(0) = {kc,qg,uu},  B(0) = {atH,atL} ----
  {
    const size_t rb = cb;
    #pragma unroll
    for (int idx = t; idx < 1024; idx += 256) {
      const int row = idx >> 4, c16 = (idx & 15)*8;
      const size_t go = (rb + row)*DK + c16;
      cpa16(&s.kcH[row][c16], g_kcH + go);
      cpa16(&s.kcL[row][c16], g_kcL + go);
      cpa16(&s.qgH[row][c16], g_qgH + go);
      cpa16(&s.qgL[row][c16], g_qgL + go);
    }
    #pragma unroll
    for (int idx = t; idx < 512; idx += 256) {
      const int row = idx >> 3, c4 = (idx & 7)*4;
      cpa16(&s.uu[row][c4], g_u + (rb + row)*DK + v0 + c4);
    }
    cpa_commit();
    #pragma unroll
    for (int idx = t; idx < 1024; idx += 256) {
      const int half = idx >> 9;
      const int row = (idx & 511) >> 3, c16 = (idx & 7)*8;
      const size_t go = rb*CC + (size_t)row*CC + c16;
      cpa16(half ? &s.atL[row][c16] : &s.atH[row][c16],
            (half ? g_atL : g_atH) + go);
    }
    cpa_commit();
  }

  for (int n = 0; n < NCH; n++) {
    const size_t rb = cb + n*CC;
    __syncthreads();  // (1) prev-chunk D + convert done; kn buffer free

    // ---- C(n): kn hi/lo ----
    #pragma unroll
    for (int idx = t; idx < 1024; idx += 256) {
      const int row = idx >> 4, c16 = (idx & 15)*8;
      const size_t go = (rb + row)*DK + c16;
      cpa16(&s.knH[row][c16], g_knH + go);
      cpa16(&s.knL[row][c16], g_knL + go);
    }
    cpa_commit();
    cpa_wait<2>();    // A(n): kc/qg/uu landed
    __syncthreads();  // (2)
    if (t < CC) {
      const float gl = g_gc[rb + CC - 1];
      s.w[t] = __expf(gl - g_gc[rb + t]);
      if (t == CC-1) s.elv = __expf(gl);
    }

    // ---- stage B (WMMA): va = kc@stT^T ; oa = qg@stT^T (oa kept in regs) ----
    wmma::fragment<wmma::accumulator, 16, 16, 16, float> accO;
    {
      wmma::fragment<wmma::accumulator, 16, 16, 16, float> accV;
      wmma::fill_fragment(accV, 0.f);
      wmma::fill_fragment(accO, 0.f);
      #pragma unroll 1
      for (int ks = 0; ks < 8; ks++) {
        wmma::fragment<wmma::matrix_a, 16, 16, 16, __nv_bfloat16, wmma::row_major> aH, aL, qH, qL;
        wmma::fragment<wmma::matrix_b, 16, 16, 16, __nv_bfloat16, wmma::col_major> bH, bL;
        wmma::load_matrix_sync(aH, &s.kcH[wmi*16][ks*16], CTS);
        wmma::load_matrix_sync(aL, &s.kcL[wmi*16][ks*16], CTS);
        wmma::load_matrix_sync(qH, &s.qgH[wmi*16][ks*16], CTS);
        wmma::load_matrix_sync(qL, &s.qgL[wmi*16][ks*16], CTS);
        wmma::load_matrix_sync(bH, &s.stH[wni*16][ks*16], 136);
        wmma::load_matrix_sync(bL, &s.stL[wni*16][ks*16], 136);
        wmma::mma_sync(accV, aH, bH, accV);
        wmma::mma_sync(accO, qH, bH, accO);
        wmma::mma_sync(accV, aH, bL, accV);
        wmma::mma_sync(accO, qH, bL, accO);
        wmma::mma_sync(accV, aL, bH, accV);
        wmma::mma_sync(accO, qL, bH, accO);
      }
      wmma::store_matrix_sync(&s.vn[wmi*16][wni*16], accV, 36, wmma::mem_row_major);
    }
    __syncthreads();  // (3)

    // ---- epilogue: vn = uu - va -> bf16 hi/lo [j][v]; vnw -> bf16 T [v][i] ----
    {
      #pragma unroll
      for (int a = 0; a < 4; a++) {
        const int i = r0 + a;
        const float2 u2 = *(const float2*)&s.uu[i][vv];
        const float2 va2 = *(const float2*)&s.vn[i][vv];
        const float v0f = u2.x - va2.x, v1f = u2.y - va2.y;
        const __nv_bfloat16 nh0 = __float2bfloat16(v0f);
        const __nv_bfloat16 nh1 = __float2bfloat16(v1f);
        s.vnH[i][vv]   = nh0;
        s.vnH[i][vv+1] = nh1;
        s.vnL[i][vv]   = __float2bfloat16(v0f - __bfloat162float(nh0));
        s.vnL[i][vv+1] = __float2bfloat16(v1f - __bfloat162float(nh1));
        const float wi = s.w[i];
        const float w0 = v0f * wi, w1 = v1f * wi;
        const __nv_bfloat16 h0 = __float2bfloat16(w0);
        const __nv_bfloat16 h1 = __float2bfloat16(w1);
        s.vwH[vv  ][i] = h0; s.vwL[vv  ][i] = __float2bfloat16(w0 - __bfloat162float(h0));
        s.vwH[vv+1][i] = h1; s.vwL[vv+1][i] = __float2bfloat16(w1 - __bfloat162float(h1));
      }
    }
    __syncthreads();  // (4) kc/qg/uu dead

    // ---- A(n+1): kc,qg,uu ----
    if (n + 1 < NCH) {
      const size_t rb1 = rb + CC;
      #pragma unroll
      for (int idx = t; idx < 1024; idx += 256) {
        const int row = idx >> 4, c16 = (idx & 15)*8;
        const size_t go = (rb1 + row)*DK + c16;
        cpa16(&s.kcH[row][c16], g_kcH + go);
        cpa16(&s.kcL[row][c16], g_kcL + go);
        cpa16(&s.qgH[row][c16], g_qgH + go);
        cpa16(&s.qgL[row][c16], g_qgL + go);
      }
      #pragma unroll
      for (int idx = t; idx < 512; idx += 256) {
        const int row = idx >> 3, c4 = (idx & 7)*4;
        cpa16(&s.uu[row][c4], g_u + (rb1 + row)*DK + v0 + c4);
      }
    }
    cpa_commit();
    cpa_wait<2>();    // B(n): atH/atL landed
    __syncthreads();  // (4b)

    // ---- stage C (WMMA): accO += attn @ vn (ks <= wmi) ; store to out ----
    {
      #pragma unroll 1
      for (int ks = 0; ks <= wmi; ks++) {
        wmma::fragment<wmma::matrix_a, 16, 16, 16, __nv_bfloat16, wmma::row_major> aH, aL;
        wmma::fragment<wmma::matrix_b, 16, 16, 16, __nv_bfloat16, wmma::row_major> bH, bL;
        wmma::load_matrix_sync(aH, &s.atH[wmi*16][ks*16], ATS);
        wmma::load_matrix_sync(aL, &s.atL[wmi*16][ks*16], ATS);
        wmma::load_matrix_sync(bH, &s.vnH[ks*16][wni*16], VNS);
        wmma::load_matrix_sync(bL, &s.vnL[ks*16][wni*16], VNS);
        wmma::mma_sync(accO, aH, bH, accO);
        wmma::mma_sync(accO, aH, bL, accO);
        wmma::mma_sync(accO, aL, bH, accO);
      }
      float* obase = out + ((size_t)(b*Ssz + n*CC + wmi*16)*Hsz + h)*DK + v0 + wni*16;
      wmma::store_matrix_sync(obase, accO, Hsz*DK, wmma::mem_row_major);
    }
    __syncthreads();  // (5) atH/atL dead

    // ---- B(n+1): atH,atL ----
    if (n + 1 < NCH) {
      const size_t rb1 = rb + CC;
      #pragma unroll
      for (int idx = t; idx < 1024; idx += 256) {
        const int half = idx >> 9;
        const int row = (idx & 511) >> 3, c16 = (idx & 7)*8;
        const size_t go = rb1*CC + (size_t)row*CC + c16;
        cpa16(half ? &s.atL[row][c16] : &s.atH[row][c16],
              (half ? g_atL : g_atH) + go);
      }
    }
    cpa_commit();
    cpa_wait<2>();    // C(n): kn landed
    __syncthreads();  // (5b)

    // ---- stage D (WMMA): stT = el*stT + vnwT @ kn ----
    {
      const float el = s.elv;
      const int ni0 = (warp & 3)*2;
      wmma::fragment<wmma::accumulator, 16, 16, 16, float> accD[2];
      #pragma unroll
      for (int sub = 0; sub < 2; sub++) {
        wmma::load_matrix_sync(accD[sub], &s.stF[dmi*16][(ni0+sub)*16], 132, wmma::mem_row_major);
        #pragma unroll
        for (int e = 0; e < accD[sub].num_elements; e++) accD[sub].x[e] *= el;
      }
      #pragma unroll 1
      for (int ks = 0; ks < 4; ks++) {
        wmma::fragment<wmma::matrix_a, 16, 16, 16, __nv_bfloat16, wmma::row_major> aH, aL;
        wmma::load_matrix_sync(aH, &s.vwH[dmi*16][ks*16], 72);
        wmma::load_matrix_sync(aL, &s.vwL[dmi*16][ks*16], 72);
        #pragma unroll
        for (int sub = 0; sub < 2; sub++) {
          wmma::fragment<wmma::matrix_b, 16, 16, 16, __nv_bfloat16, wmma::row_major> bH, bL;
          wmma::load_matrix_sync(bH, &s.knH[ks*16][(ni0+sub)*16], CTS);
          wmma::load_matrix_sync(bL, &s.knL[ks*16][(ni0+sub)*16], CTS);
          wmma::mma_sync(accD[sub], aH, bH, accD[sub]);
          wmma::mma_sync(accD[sub], aH, bL, accD[sub]);
          wmma::mma_sync(accD[sub], aL, bH, accD[sub]);
        }
      }
      #pragma unroll
      for (int sub = 0; sub < 2; sub++)
        wmma::store_matrix_sync(&s.stF[dmi*16][(ni0+sub)*16], accD[sub], 132, wmma::mem_row_major);
    }
    __syncthreads();  // (6)

    // ---- convert stF -> stH/stL (bf16 hi/lo) ----
    {
      #pragma unroll
      for (int c = 0; c < 16; c += 4) {
        const float4 f = *(const float4*)&s.stF[cvr][cvc + c];
        const float fm[4] = {f.x, f.y, f.z, f.w};
        #pragma unroll
        for (int e = 0; e < 4; e++) {
          const __nv_bfloat16 hi = __float2bfloat16(fm[e]);
          s.stH[cvr][cvc + c + e] = hi;
          s.stL[cvr][cvc + c + e] = __float2bfloat16(fm[e] - __bfloat162float(hi));
        }
      }
    }
  }
}

// ================= launch =================
extern "C" void kernel_launch(void* const* d_in, const int* in_sizes, int n_in,
                              void* d_out, int out_size) {
  const float* q    = (const float*)d_in[0];
  const float* k    = (const float*)d_in[1];
  const float* v    = (const float*)d_in[2];
  const float* g    = (const float*)d_in[3];
  const float* beta = (const float*)d_in[4];
  float* out = (float*)d_out;

  cudaFuncSetAttribute((const void*)phase1_kernel,
                       cudaFuncAttributeMaxDynamicSharedMemorySize, P1_BYTES);
  cudaFuncSetAttribute((const void*)phase2_kernel,
                       cudaFuncAttributeMaxDynamicSharedMemorySize, (int)sizeof(P2S));

  phase1_kernel<<<BH*NCH, 256, P1_BYTES>>>(q, k, v, g, beta);
  phase2_kernel<<<BH*SPLIT, 256, sizeof(P2S)>>>(out);
}